// round 6
// baseline (speedup 1.0000x reference)
#include <cuda_runtime.h>
#include <cuda_bf16.h>
#include <math.h>
#include <stdint.h>

#define N_PTS 8192
#define HDIM  512
#define NM1   8191
#define DEPTHM1 5

// ---------------- scratch (device globals; no allocations allowed) ----------
__device__ __align__(16) __nv_bfloat16 g_Ahi0[N_PTS * HDIM];
__device__ __align__(16) __nv_bfloat16 g_Alo0[N_PTS * HDIM];
__device__ __align__(16) __nv_bfloat16 g_Ahi1[N_PTS * HDIM];
__device__ __align__(16) __nv_bfloat16 g_Alo1[N_PTS * HDIM];
__device__ __align__(16) __nv_bfloat16 g_Whi[DEPTHM1 * HDIM * HDIM];  // [l][k][n]
__device__ __align__(16) __nv_bfloat16 g_Wlo[DEPTHM1 * HDIM * HDIM];
__device__ float  g_y[N_PTS * 5];
__device__ float  g_dpsi[NM1 * 5];
__device__ float  g_ws[NM1];
__device__ float  g_conv[NM1 * 5];
__device__ float  g_par[6];
__device__ double g_acc;

__device__ __forceinline__ float tanh_acc(float x) {
    float ax = fabsf(x);
    float u = __expf(-2.0f * ax);
    float t = __fdividef(1.0f - u, 1.0f + u);
    return copysignf(t, x);
}

// ---------------- setup ------------------------------------------------------
__global__ void setup_kernel(const float* __restrict__ rb, const float* __restrict__ rs,
                             const float* __restrict__ rg, const float* __restrict__ rm,
                             const float* __restrict__ za_p) {
    int tid = threadIdx.x;
    float alpha = 0.6f + 0.4f * (1.0f / (1.0f + expf(-za_p[0])));
    if (tid == 0) {
        g_par[0] = alpha;
        g_par[1] = log1pf(expf(rb[0]));
        g_par[2] = log1pf(expf(rs[0]));
        g_par[3] = log1pf(expf(rg[0]));
        g_par[4] = log1pf(expf(rm[0]));
        g_par[5] = powf(0.1f, -alpha) / expf(lgammaf(2.0f - alpha));
        g_acc    = 0.0;
    }
    double ex = 1.0 - (double)alpha;
    for (int r = tid; r < NM1; r += blockDim.x) {
        double w = pow((double)(r + 1), ex);
        if (r > 0) w -= pow((double)r, ex);
        g_ws[r] = (float)w;
    }
    for (int i = tid; i < NM1 * 5; i += blockDim.x) g_conv[i] = 0.0f;
}

// ---------------- split weights into bf16 hi/lo ------------------------------
__global__ void wsplit_kernel(const float* __restrict__ W) {
    int i = blockIdx.x * 256 + threadIdx.x;
    if (i < DEPTHM1 * HDIM * HDIM) {
        float w = W[i];
        __nv_bfloat16 h = __float2bfloat16(w);
        g_Whi[i] = h;
        g_Wlo[i] = __float2bfloat16(w - __bfloat162float(h));
    }
}

// ---------------- layer 0 ----------------------------------------------------
__global__ void layer0_kernel(const float* __restrict__ t, const float* __restrict__ W_in,
                              const float* __restrict__ b_in) {
    int idx = blockIdx.x * blockDim.x + threadIdx.x;
    if (idx >= N_PTS * HDIM) return;
    float h = tanh_acc(t[idx >> 9] * W_in[idx & 511] + b_in[idx & 511]);
    __nv_bfloat16 hi = __float2bfloat16(h);
    g_Ahi0[idx] = hi;
    g_Alo0[idx] = __float2bfloat16(h - __bfloat162float(hi));
}

// ---------------- tensor-core GEMM (bf16x3) + bias + tanh --------------------
// CTA 128m x 128n, BK=32, 4-stage cp.async, 8 warps (2m x 4n), warp 64m x 32n.
// Stage 32KB: A_hi[8K: two 4K k16-slabs] A_lo[8K] B_hi[8K] B_lo[8K].
#define STG 32768
#define GEMM_SMEM (4 * STG)

#define LDSM4(r, addr) asm volatile( \
    "ldmatrix.sync.aligned.m8n8.x4.shared.b16 {%0,%1,%2,%3}, [%4];" \
    : "=r"(r[0]), "=r"(r[1]), "=r"(r[2]), "=r"(r[3]) : "r"(addr))

#define LDSM4T(r, addr) asm volatile( \
    "ldmatrix.sync.aligned.m8n8.x4.trans.shared.b16 {%0,%1,%2,%3}, [%4];" \
    : "=r"(r[0]), "=r"(r[1]), "=r"(r[2]), "=r"(r[3]) : "r"(addr))

#define MMA16816(d, a, b0, b1) asm volatile( \
    "mma.sync.aligned.m16n8k16.row.col.f32.bf16.bf16.f32 " \
    "{%0,%1,%2,%3},{%4,%5,%6,%7},{%8,%9},{%0,%1,%2,%3};" \
    : "+f"(d[0]), "+f"(d[1]), "+f"(d[2]), "+f"(d[3]) \
    : "r"(a[0]), "r"(a[1]), "r"(a[2]), "r"(a[3]), "r"(b0), "r"(b1))

__device__ __forceinline__ void cp16(uint32_t dst, const void* src) {
    asm volatile("cp.async.cg.shared.global [%0], [%1], 16;" :: "r"(dst), "l"(src));
}

__global__ __launch_bounds__(256, 1)
void gemm_mma2_kernel(const __nv_bfloat16* __restrict__ Ahi, const __nv_bfloat16* __restrict__ Alo,
                      const __nv_bfloat16* __restrict__ Bhi, const __nv_bfloat16* __restrict__ Blo,
                      const float* __restrict__ bias,
                      __nv_bfloat16* __restrict__ Chi, __nv_bfloat16* __restrict__ Clo) {
    extern __shared__ __align__(128) unsigned char smem[];
    const int tid  = threadIdx.x;
    const int lane = tid & 31;
    const int wid  = tid >> 5;
    const int wm   = wid & 1;     // m offset 64*wm
    const int wn   = wid >> 1;    // n offset 32*wn
    const int rowBase = blockIdx.y * 128;
    const int colBase = blockIdx.x * 128;
    const uint32_t sb = (uint32_t)__cvta_generic_to_shared(smem);

    // ---- per-thread cp.async chunk mapping (8 x 16B per stage) ----
    // A: chunks c = i*256+tid, i=0..1 -> A_hi, i=2..3 -> A_lo (512 each)
    const __nv_bfloat16* aSrc[4];
    uint32_t aOff[4];
#pragma unroll
    for (int i = 0; i < 4; i++) {
        int c  = i * 256 + tid;
        int cc = c & 511;
        int ks = cc >> 8;           // k16 slab
        int r  = (cc >> 1) & 127;   // row
        int ch = cc & 1;            // 16B chunk in slab row
        aOff[i] = (uint32_t)((c < 512 ? 0 : 8192) + ks * 4096 + r * 32 +
                             ((ch ^ ((r >> 2) & 1)) << 4));
        aSrc[i] = (c < 512 ? Ahi : Alo) + (size_t)(rowBase + r) * HDIM + ks * 16 + ch * 8;
    }
    // B: chunks c = i*256+tid, i=0..1 -> B_hi, i=2..3 -> B_lo
    const __nv_bfloat16* bSrc[4];
    uint32_t bOff[4];
#pragma unroll
    for (int i = 0; i < 4; i++) {
        int c  = i * 256 + tid;
        int cc = c & 511;
        int k  = cc >> 4;           // 0..31
        int nq = cc & 15;           // 16B chunk in 256B row
        bOff[i] = (uint32_t)(16384 + (c < 512 ? 0 : 8192) + k * 256 +
                             ((nq ^ (k & 7)) << 4));
        bSrc[i] = (c < 512 ? Bhi : Blo) + (size_t)k * HDIM + colBase + nq * 8;
    }

    float acc[4][4][4];
#pragma unroll
    for (int i = 0; i < 4; i++)
#pragma unroll
        for (int j = 0; j < 4; j++)
#pragma unroll
            for (int r = 0; r < 4; r++) acc[i][j][r] = 0.0f;

    // ---- prologue: issue stages 0..2 ----
#pragma unroll
    for (int s = 0; s < 3; s++) {
        uint32_t st = sb + s * STG;
        int k0 = s * 32;
#pragma unroll
        for (int i = 0; i < 4; i++) cp16(st + aOff[i], aSrc[i] + k0);
#pragma unroll
        for (int i = 0; i < 4; i++) cp16(st + bOff[i], bSrc[i] + (size_t)k0 * HDIM);
        asm volatile("cp.async.commit_group;");
    }

    for (int s = 0; s < 16; s++) {
        if (s < 13)      asm volatile("cp.async.wait_group 2;");
        else if (s == 13) asm volatile("cp.async.wait_group 2;");
        else if (s == 14) asm volatile("cp.async.wait_group 1;");
        else              asm volatile("cp.async.wait_group 0;");
        __syncthreads();

        if (s + 3 < 16) {   // prefetch stage s+3 into buffer (s+3)&3 (free since s-1)
            uint32_t st = sb + ((s + 3) & 3) * STG;
            int k0 = (s + 3) * 32;
#pragma unroll
            for (int i = 0; i < 4; i++) cp16(st + aOff[i], aSrc[i] + k0);
#pragma unroll
            for (int i = 0; i < 4; i++) cp16(st + bOff[i], bSrc[i] + (size_t)k0 * HDIM);
            asm volatile("cp.async.commit_group;");
        }

        const uint32_t st = sb + (s & 3) * STG;
#pragma unroll
        for (int ks = 0; ks < 2; ks++) {
            uint32_t ah[4][4], al[4][4];
#pragma unroll
            for (int i = 0; i < 4; i++) {
                int r = wm * 64 + i * 16 + (lane & 15);
                uint32_t c = ((uint32_t)(lane >> 4)) ^ ((r >> 2) & 1);
                uint32_t addr = st + ks * 4096 + r * 32 + (c << 4);
                LDSM4(ah[i], addr);
                LDSM4(al[i], addr + 8192);
            }
            uint32_t bh[2][4], bl[2][4];
#pragma unroll
            for (int j = 0; j < 2; j++) {
                int kr = lane & 15;
                uint32_t c = ((uint32_t)(wn * 4 + j * 2 + (lane >> 4))) ^ (kr & 7);
                uint32_t addr = st + 16384u + (ks * 16 + kr) * 256 + (c << 4);
                LDSM4T(bh[j], addr);
                LDSM4T(bl[j], addr + 8192);
            }
#pragma unroll
            for (int i = 0; i < 4; i++) {
#pragma unroll
                for (int j = 0; j < 2; j++) {
                    MMA16816(acc[i][2 * j],     ah[i], bh[j][0], bh[j][1]);
                    MMA16816(acc[i][2 * j + 1], ah[i], bh[j][2], bh[j][3]);
                    MMA16816(acc[i][2 * j],     ah[i], bl[j][0], bl[j][1]);
                    MMA16816(acc[i][2 * j + 1], ah[i], bl[j][2], bl[j][3]);
                    MMA16816(acc[i][2 * j],     al[i], bh[j][0], bh[j][1]);
                    MMA16816(acc[i][2 * j + 1], al[i], bh[j][2], bh[j][3]);
                }
            }
        }
        __syncthreads();
    }

    // ---- epilogue: bias + tanh + hi/lo split ----
#pragma unroll
    for (int i = 0; i < 4; i++) {
        int r0 = rowBase + wm * 64 + i * 16 + (lane >> 2);
#pragma unroll
        for (int jn = 0; jn < 4; jn++) {
            int c0 = colBase + wn * 32 + jn * 8 + (lane & 3) * 2;
            float bv0 = __ldg(bias + c0), bv1 = __ldg(bias + c0 + 1);
#pragma unroll
            for (int half = 0; half < 2; half++) {
                int r = r0 + half * 8;
                float x0 = acc[i][jn][2 * half + 0] + bv0;
                float x1 = acc[i][jn][2 * half + 1] + bv1;
                float t0 = tanh_acc(x0), t1 = tanh_acc(x1);
                __nv_bfloat16 h0 = __float2bfloat16(t0), h1 = __float2bfloat16(t1);
                __nv_bfloat162 hv; hv.x = h0; hv.y = h1;
                __nv_bfloat162 lv;
                lv.x = __float2bfloat16(t0 - __bfloat162float(h0));
                lv.y = __float2bfloat16(t1 - __bfloat162float(h1));
                *(__nv_bfloat162*)(Chi + (size_t)r * HDIM + c0) = hv;
                *(__nv_bfloat162*)(Clo + (size_t)r * HDIM + c0) = lv;
            }
        }
    }
}

// ---------------- head + softmax ---------------------------------------------
__global__ void head_kernel(const __nv_bfloat16* __restrict__ hhi,
                            const __nv_bfloat16* __restrict__ hlo,
                            const float* __restrict__ W_out, const float* __restrict__ b_out) {
    int gw = (blockIdx.x * blockDim.x + threadIdx.x) >> 5;
    int lane = threadIdx.x & 31;
    if (gw >= N_PTS) return;
    const __nv_bfloat16* hr = hhi + (size_t)gw * HDIM;
    const __nv_bfloat16* lr = hlo + (size_t)gw * HDIM;
    float a0 = 0, a1 = 0, a2 = 0, a3 = 0, a4 = 0;
    for (int k = lane; k < HDIM; k += 32) {
        float hv = __bfloat162float(hr[k]) + __bfloat162float(lr[k]);
        const float* w = W_out + k * 5;
        a0 += hv * w[0]; a1 += hv * w[1]; a2 += hv * w[2]; a3 += hv * w[3]; a4 += hv * w[4];
    }
#pragma unroll
    for (int off = 16; off; off >>= 1) {
        a0 += __shfl_down_sync(~0u, a0, off); a1 += __shfl_down_sync(~0u, a1, off);
        a2 += __shfl_down_sync(~0u, a2, off); a3 += __shfl_down_sync(~0u, a3, off);
        a4 += __shfl_down_sync(~0u, a4, off);
    }
    if (lane == 0) {
        a0 += b_out[0]; a1 += b_out[1]; a2 += b_out[2]; a3 += b_out[3]; a4 += b_out[4];
        float mx = fmaxf(fmaxf(fmaxf(a0, a1), fmaxf(a2, a3)), a4);
        float e0 = expf(a0 - mx), e1 = expf(a1 - mx), e2 = expf(a2 - mx);
        float e3 = expf(a3 - mx), e4 = expf(a4 - mx);
        float inv = 1.0f / (e0 + e1 + e2 + e3 + e4);
        g_y[gw * 5 + 0] = e0 * inv; g_y[gw * 5 + 1] = e1 * inv; g_y[gw * 5 + 2] = e2 * inv;
        g_y[gw * 5 + 3] = e3 * inv; g_y[gw * 5 + 4] = e4 * inv;
    }
}

__global__ void dpsi_kernel() {
    int idx = blockIdx.x * blockDim.x + threadIdx.x;
    if (idx < NM1 * 5) g_dpsi[idx] = g_y[idx + 5] - g_y[idx];
}

// ---------------- causal Toeplitz conv ---------------------------------------
__global__ void conv_kernel() {
    int rx = blockIdx.x, jy = blockIdx.y;
    if (jy > rx) return;
    __shared__ float sws[512];
    __shared__ float sd[256 * 5];
    int tid = threadIdx.x, m = rx * 256 + tid, j0 = jy * 256;
    {
        int j = j0 + tid;
#pragma unroll
        for (int c = 0; c < 5; c++) sd[tid * 5 + c] = (j < NM1) ? g_dpsi[j * 5 + c] : 0.0f;
    }
    int wbase = (rx - jy) * 256 - 255;
    for (int k = tid; k < 512; k += 256) {
        int wi = wbase + k;
        sws[k] = (wi >= 0 && wi < NM1) ? g_ws[wi] : 0.0f;
    }
    __syncthreads();
    float a0 = 0, a1 = 0, a2 = 0, a3 = 0, a4 = 0;
#pragma unroll 8
    for (int jj = 0; jj < 256; jj++) {
        float w = sws[tid + 255 - jj];
        const float* d = &sd[jj * 5];
        a0 += w * d[0]; a1 += w * d[1]; a2 += w * d[2]; a3 += w * d[3]; a4 += w * d[4];
    }
    if (m < NM1) {
        atomicAdd(&g_conv[m * 5 + 0], a0); atomicAdd(&g_conv[m * 5 + 1], a1);
        atomicAdd(&g_conv[m * 5 + 2], a2); atomicAdd(&g_conv[m * 5 + 3], a3);
        atomicAdd(&g_conv[m * 5 + 4], a4);
    }
}

// ---------------- residual + loss --------------------------------------------
__global__ void resid_kernel() {
    __shared__ double sm[256];
    int tid = threadIdx.x, row = blockIdx.x * 256 + tid;
    double local = 0.0;
    if (row < N_PTS) {
        float beta = g_par[1], sg = g_par[2], gm = g_par[3], mu = g_par[4], Cc = g_par[5];
        float ys = g_y[row * 5 + 0], ye = g_y[row * 5 + 1], yi = g_y[row * 5 + 2], yd = g_y[row * 5 + 4];
        float inf = beta * ys * yi / (1.0f - yd);
        float f0 = -inf, f1 = inf - sg * ye, f2 = sg * ye - (gm + mu) * yi, f3 = gm * yi, f4 = mu * yi;
        float d0 = 0, d1 = 0, d2 = 0, d3 = 0, d4 = 0;
        if (row > 0) {
            const float* cv = &g_conv[(row - 1) * 5];
            d0 = Cc * cv[0]; d1 = Cc * cv[1]; d2 = Cc * cv[2]; d3 = Cc * cv[3]; d4 = Cc * cv[4];
        }
        float r0 = d0 - f0, r1 = d1 - f1, r2 = d2 - f2, r3 = d3 - f3, r4 = d4 - f4;
        local = (double)r0 * r0 + (double)r1 * r1 + (double)r2 * r2 + (double)r3 * r3 + (double)r4 * r4;
    }
    sm[tid] = local;
    __syncthreads();
    for (int s2 = 128; s2; s2 >>= 1) {
        if (tid < s2) sm[tid] += sm[tid + s2];
        __syncthreads();
    }
    if (tid == 0) atomicAdd(&g_acc, sm[0]);
}

__global__ void finalize_kernel(float* __restrict__ out) {
    out[0] = (float)(g_acc / (double)(N_PTS * 5));
}

// ---------------- launch -----------------------------------------------------
extern "C" void kernel_launch(void* const* d_in, const int* in_sizes, int n_in,
                              void* d_out, int out_size) {
    const float* t      = (const float*)d_in[0];
    const float* W_in   = (const float*)d_in[1];
    const float* b_in   = (const float*)d_in[2];
    const float* Wh     = (const float*)d_in[3];   // [5,512,512]
    const float* bh     = (const float*)d_in[4];
    const float* W_out  = (const float*)d_in[5];
    const float* b_out  = (const float*)d_in[6];
    const float* rbeta  = (const float*)d_in[7];
    const float* rsigma = (const float*)d_in[8];
    const float* rgamma = (const float*)d_in[9];
    const float* rmu    = (const float*)d_in[10];
    const float* zalpha = (const float*)d_in[11];
    float* out = (float*)d_out;

    static bool inited = false;
    static __nv_bfloat16 *ahi0, *alo0, *ahi1, *alo1, *whi, *wlo;
    if (!inited) {
        cudaGetSymbolAddress((void**)&ahi0, g_Ahi0);
        cudaGetSymbolAddress((void**)&alo0, g_Alo0);
        cudaGetSymbolAddress((void**)&ahi1, g_Ahi1);
        cudaGetSymbolAddress((void**)&alo1, g_Alo1);
        cudaGetSymbolAddress((void**)&whi, g_Whi);
        cudaGetSymbolAddress((void**)&wlo, g_Wlo);
        cudaFuncSetAttribute(gemm_mma2_kernel,
                             cudaFuncAttributeMaxDynamicSharedMemorySize, GEMM_SMEM);
        inited = true;
    }

    setup_kernel<<<1, 256>>>(rbeta, rsigma, rgamma, rmu, zalpha);
    wsplit_kernel<<<(DEPTHM1 * HDIM * HDIM + 255) / 256, 256>>>(Wh);
    layer0_kernel<<<(N_PTS * HDIM) / 256, 256>>>(t, W_in, b_in);

    dim3 gg(4, 64);   // (512/128, 8192/128)
    const int WW = HDIM * HDIM;
    gemm_mma2_kernel<<<gg, 256, GEMM_SMEM>>>(ahi0, alo0, whi + 0 * WW, wlo + 0 * WW, bh + 0 * HDIM, ahi1, alo1);
    gemm_mma2_kernel<<<gg, 256, GEMM_SMEM>>>(ahi1, alo1, whi + 1 * WW, wlo + 1 * WW, bh + 1 * HDIM, ahi0, alo0);
    gemm_mma2_kernel<<<gg, 256, GEMM_SMEM>>>(ahi0, alo0, whi + 2 * WW, wlo + 2 * WW, bh + 2 * HDIM, ahi1, alo1);
    gemm_mma2_kernel<<<gg, 256, GEMM_SMEM>>>(ahi1, alo1, whi + 3 * WW, wlo + 3 * WW, bh + 3 * HDIM, ahi0, alo0);
    gemm_mma2_kernel<<<gg, 256, GEMM_SMEM>>>(ahi0, alo0, whi + 4 * WW, wlo + 4 * WW, bh + 4 * HDIM, ahi1, alo1);

    head_kernel<<<N_PTS / 8, 256>>>(ahi1, alo1, W_out, b_out);
    dpsi_kernel<<<(NM1 * 5 + 255) / 256, 256>>>();
    conv_kernel<<<dim3(32, 32), 256>>>();
    resid_kernel<<<N_PTS / 256, 256>>>();
    finalize_kernel<<<1, 1>>>(out);
}

// round 7
// speedup vs baseline: 1.3067x; 1.3067x over previous
#include <cuda_runtime.h>
#include <cuda_bf16.h>
#include <cuda_fp16.h>
#include <math.h>
#include <stdint.h>

#define N_PTS 8192
#define HDIM  512
#define NM1   8191
#define DEPTHM1 5

// ---------------- scratch (device globals; no allocations allowed) ----------
__device__ __align__(16) __half g_Ahi0[N_PTS * HDIM];
__device__ __align__(16) __half g_Alo0[N_PTS * HDIM];
__device__ __align__(16) __half g_Ahi1[N_PTS * HDIM];
__device__ __align__(16) __half g_Alo1[N_PTS * HDIM];
__device__ __align__(16) __half g_Wh[DEPTHM1 * HDIM * HDIM];  // [l][k][n] fp16
__device__ float  g_y[N_PTS * 5];
__device__ float  g_dpsi[NM1 * 5];
__device__ float  g_ws[NM1];
__device__ float  g_conv[NM1 * 5];
__device__ float  g_par[6];
__device__ double g_acc;

__device__ __forceinline__ float tanh_acc(float x) {
    float ax = fabsf(x);
    float u = __expf(-2.0f * ax);
    float t = __fdividef(1.0f - u, 1.0f + u);
    return copysignf(t, x);
}

// ---------------- setup ------------------------------------------------------
__global__ void setup_kernel(const float* __restrict__ rb, const float* __restrict__ rs,
                             const float* __restrict__ rg, const float* __restrict__ rm,
                             const float* __restrict__ za_p) {
    int tid = threadIdx.x;
    float alpha = 0.6f + 0.4f * (1.0f / (1.0f + expf(-za_p[0])));
    if (tid == 0) {
        g_par[0] = alpha;
        g_par[1] = log1pf(expf(rb[0]));
        g_par[2] = log1pf(expf(rs[0]));
        g_par[3] = log1pf(expf(rg[0]));
        g_par[4] = log1pf(expf(rm[0]));
        g_par[5] = powf(0.1f, -alpha) / expf(lgammaf(2.0f - alpha));
        g_acc    = 0.0;
    }
    double ex = 1.0 - (double)alpha;
    for (int r = tid; r < NM1; r += blockDim.x) {
        double w = pow((double)(r + 1), ex);
        if (r > 0) w -= pow((double)r, ex);
        g_ws[r] = (float)w;
    }
    for (int i = tid; i < NM1 * 5; i += blockDim.x) g_conv[i] = 0.0f;
}

// ---------------- weights -> fp16 -------------------------------------------
__global__ void wsplit_kernel(const float* __restrict__ W) {
    int i = blockIdx.x * 256 + threadIdx.x;
    if (i < DEPTHM1 * HDIM * HDIM) g_Wh[i] = __float2half(W[i]);
}

// ---------------- layer 0 ----------------------------------------------------
__global__ void layer0_kernel(const float* __restrict__ t, const float* __restrict__ W_in,
                              const float* __restrict__ b_in) {
    int idx = blockIdx.x * blockDim.x + threadIdx.x;
    if (idx >= N_PTS * HDIM) return;
    float h = tanh_acc(t[idx >> 9] * W_in[idx & 511] + b_in[idx & 511]);
    __half hi = __float2half(h);
    g_Ahi0[idx] = hi;
    g_Alo0[idx] = __float2half(h - __half2float(hi));
}

// ---------------- tensor-core GEMM (fp16x2) + bias + tanh --------------------
// C = tanh(A@W + bias); A hi/lo fp16, W fp16. Tile 64m x 128n, BK=16, 8 warps.
// Stage 8KB: A_hi 2K | A_lo 2K | B 4K. Two stages.
#define STAGE_BYTES 8192

#define LDSM4(r, addr) asm volatile( \
    "ldmatrix.sync.aligned.m8n8.x4.shared.b16 {%0,%1,%2,%3}, [%4];" \
    : "=r"(r[0]), "=r"(r[1]), "=r"(r[2]), "=r"(r[3]) : "r"(addr))

#define LDSM4T(r, addr) asm volatile( \
    "ldmatrix.sync.aligned.m8n8.x4.trans.shared.b16 {%0,%1,%2,%3}, [%4];" \
    : "=r"(r[0]), "=r"(r[1]), "=r"(r[2]), "=r"(r[3]) : "r"(addr))

#define MMAH(d, a, b0, b1) asm volatile( \
    "mma.sync.aligned.m16n8k16.row.col.f32.f16.f16.f32 " \
    "{%0,%1,%2,%3},{%4,%5,%6,%7},{%8,%9},{%0,%1,%2,%3};" \
    : "+f"(d[0]), "+f"(d[1]), "+f"(d[2]), "+f"(d[3]) \
    : "r"(a[0]), "r"(a[1]), "r"(a[2]), "r"(a[3]), "r"(b0), "r"(b1))

__device__ __forceinline__ void cp16(uint32_t dst, const void* src) {
    asm volatile("cp.async.cg.shared.global [%0], [%1], 16;" :: "r"(dst), "l"(src));
}

__global__ __launch_bounds__(256, 3)
void gemm_fp16_kernel(const __half* __restrict__ Ahi, const __half* __restrict__ Alo,
                      const __half* __restrict__ B,
                      const float* __restrict__ bias,
                      __half* __restrict__ Chi, __half* __restrict__ Clo) {
    __shared__ __align__(128) unsigned char smem[2 * STAGE_BYTES];
    const int tid  = threadIdx.x;
    const int lane = tid & 31;
    const int wid  = tid >> 5;
    const int wm   = wid & 1;     // m offset 32*wm
    const int wn   = wid >> 1;    // n offset 32*wn
    const int rowBase = blockIdx.y * 64;
    const int colBase = blockIdx.x * 128;
    const uint32_t smemBase = (uint32_t)__cvta_generic_to_shared(smem);

    // A: threads 0-127 load A_hi, 128-255 load A_lo; row=(t&127)>>1, kq=(t&1)*8
    const int arow = (tid & 127) >> 1;
    const int akq  = (tid & 1) * 8;
    const __half* aSrc = ((tid < 128) ? Ahi : Alo) + (size_t)(rowBase + arow) * HDIM + akq;
    const uint32_t aDst = (uint32_t)((tid < 128) ? 0 : 2048) + arow * 32 +
                          ((((uint32_t)(akq >> 3)) ^ ((arow >> 2) & 1)) << 4);
    // B: k=t>>4 (0..15), nq=(t&15)*8  (one 16B chunk per thread)
    const int bk  = tid >> 4;
    const int bnq = (tid & 15) * 8;
    const __half* bSrc = B + (size_t)bk * HDIM + colBase + bnq;
    const uint32_t bDst = 4096u + bk * 256 + ((((uint32_t)(bnq >> 3)) ^ (bk & 7)) << 4);

    float acc[2][4][4];
#pragma unroll
    for (int i = 0; i < 2; i++)
#pragma unroll
        for (int j = 0; j < 4; j++)
#pragma unroll
            for (int r = 0; r < 4; r++) acc[i][j][r] = 0.0f;

    // prologue: stage 0
    {
        cp16(smemBase + aDst, aSrc);
        cp16(smemBase + bDst, bSrc);
        asm volatile("cp.async.commit_group;");
    }

#pragma unroll 2
    for (int s = 0; s < 32; s++) {
        if (s < 31) {
            uint32_t st = smemBase + ((s + 1) & 1) * STAGE_BYTES;
            cp16(st + aDst, aSrc + ((s + 1) << 4));
            cp16(st + bDst, bSrc + ((size_t)(s + 1) << 13));
            asm volatile("cp.async.commit_group;");
            asm volatile("cp.async.wait_group 1;");
        } else {
            asm volatile("cp.async.wait_group 0;");
        }
        __syncthreads();

        const uint32_t st = smemBase + (s & 1) * STAGE_BYTES;
        uint32_t a_hi[2][4], a_lo[2][4];
#pragma unroll
        for (int i = 0; i < 2; i++) {
            int r = wm * 32 + i * 16 + (lane & 15);
            uint32_t c = ((uint32_t)(lane >> 4)) ^ ((r >> 2) & 1);
            uint32_t addr = st + r * 32 + (c << 4);
            LDSM4(a_hi[i], addr);
            LDSM4(a_lo[i], addr + 2048);
        }
        uint32_t b[2][4];
#pragma unroll
        for (int j = 0; j < 2; j++) {
            int kr = lane & 15;
            uint32_t c = ((uint32_t)(wn * 4 + j * 2 + (lane >> 4))) ^ (kr & 7);
            uint32_t addr = st + 4096u + kr * 256 + (c << 4);
            LDSM4T(b[j], addr);
        }
#pragma unroll
        for (int i = 0; i < 2; i++) {
#pragma unroll
            for (int j = 0; j < 2; j++) {
                MMAH(acc[i][2 * j],     a_hi[i], b[j][0], b[j][1]);
                MMAH(acc[i][2 * j + 1], a_hi[i], b[j][2], b[j][3]);
                MMAH(acc[i][2 * j],     a_lo[i], b[j][0], b[j][1]);
                MMAH(acc[i][2 * j + 1], a_lo[i], b[j][2], b[j][3]);
            }
        }
        __syncthreads();
    }

    // ---- epilogue: bias + tanh + hi/lo split ----
#pragma unroll
    for (int i = 0; i < 2; i++) {
        int r0 = rowBase + wm * 32 + i * 16 + (lane >> 2);
#pragma unroll
        for (int jj = 0; jj < 4; jj++) {
            int c0 = colBase + wn * 32 + jj * 8 + (lane & 3) * 2;
            float bv0 = __ldg(bias + c0), bv1 = __ldg(bias + c0 + 1);
#pragma unroll
            for (int half = 0; half < 2; half++) {
                int r = r0 + half * 8;
                float x0 = acc[i][jj][2 * half + 0] + bv0;
                float x1 = acc[i][jj][2 * half + 1] + bv1;
                float t0 = tanh_acc(x0), t1 = tanh_acc(x1);
                __half h0 = __float2half(t0), h1 = __float2half(t1);
                __half2 hv; hv.x = h0; hv.y = h1;
                __half2 lv;
                lv.x = __float2half(t0 - __half2float(h0));
                lv.y = __float2half(t1 - __half2float(h1));
                *(__half2*)(Chi + (size_t)r * HDIM + c0) = hv;
                *(__half2*)(Clo + (size_t)r * HDIM + c0) = lv;
            }
        }
    }
}

// ---------------- head + softmax ---------------------------------------------
__global__ void head_kernel(const __half* __restrict__ hhi, const __half* __restrict__ hlo,
                            const float* __restrict__ W_out, const float* __restrict__ b_out) {
    int gw = (blockIdx.x * blockDim.x + threadIdx.x) >> 5;
    int lane = threadIdx.x & 31;
    if (gw >= N_PTS) return;
    const __half* hr = hhi + (size_t)gw * HDIM;
    const __half* lr = hlo + (size_t)gw * HDIM;
    float a0 = 0, a1 = 0, a2 = 0, a3 = 0, a4 = 0;
    for (int k = lane; k < HDIM; k += 32) {
        float hv = __half2float(hr[k]) + __half2float(lr[k]);
        const float* w = W_out + k * 5;
        a0 += hv * w[0]; a1 += hv * w[1]; a2 += hv * w[2]; a3 += hv * w[3]; a4 += hv * w[4];
    }
#pragma unroll
    for (int off = 16; off; off >>= 1) {
        a0 += __shfl_down_sync(~0u, a0, off); a1 += __shfl_down_sync(~0u, a1, off);
        a2 += __shfl_down_sync(~0u, a2, off); a3 += __shfl_down_sync(~0u, a3, off);
        a4 += __shfl_down_sync(~0u, a4, off);
    }
    if (lane == 0) {
        a0 += b_out[0]; a1 += b_out[1]; a2 += b_out[2]; a3 += b_out[3]; a4 += b_out[4];
        float mx = fmaxf(fmaxf(fmaxf(a0, a1), fmaxf(a2, a3)), a4);
        float e0 = expf(a0 - mx), e1 = expf(a1 - mx), e2 = expf(a2 - mx);
        float e3 = expf(a3 - mx), e4 = expf(a4 - mx);
        float inv = 1.0f / (e0 + e1 + e2 + e3 + e4);
        g_y[gw * 5 + 0] = e0 * inv; g_y[gw * 5 + 1] = e1 * inv; g_y[gw * 5 + 2] = e2 * inv;
        g_y[gw * 5 + 3] = e3 * inv; g_y[gw * 5 + 4] = e4 * inv;
    }
}

__global__ void dpsi_kernel() {
    int idx = blockIdx.x * blockDim.x + threadIdx.x;
    if (idx < NM1 * 5) g_dpsi[idx] = g_y[idx + 5] - g_y[idx];
}

// ---------------- causal Toeplitz conv ---------------------------------------
__global__ void conv_kernel() {
    int rx = blockIdx.x, jy = blockIdx.y;
    if (jy > rx) return;
    __shared__ float sws[512];
    __shared__ float sd[256 * 5];
    int tid = threadIdx.x, m = rx * 256 + tid, j0 = jy * 256;
    {
        int j = j0 + tid;
#pragma unroll
        for (int c = 0; c < 5; c++) sd[tid * 5 + c] = (j < NM1) ? g_dpsi[j * 5 + c] : 0.0f;
    }
    int wbase = (rx - jy) * 256 - 255;
    for (int k = tid; k < 512; k += 256) {
        int wi = wbase + k;
        sws[k] = (wi >= 0 && wi < NM1) ? g_ws[wi] : 0.0f;
    }
    __syncthreads();
    float a0 = 0, a1 = 0, a2 = 0, a3 = 0, a4 = 0;
#pragma unroll 8
    for (int jj = 0; jj < 256; jj++) {
        float w = sws[tid + 255 - jj];
        const float* d = &sd[jj * 5];
        a0 += w * d[0]; a1 += w * d[1]; a2 += w * d[2]; a3 += w * d[3]; a4 += w * d[4];
    }
    if (m < NM1) {
        atomicAdd(&g_conv[m * 5 + 0], a0); atomicAdd(&g_conv[m * 5 + 1], a1);
        atomicAdd(&g_conv[m * 5 + 2], a2); atomicAdd(&g_conv[m * 5 + 3], a3);
        atomicAdd(&g_conv[m * 5 + 4], a4);
    }
}

// ---------------- residual + loss --------------------------------------------
__global__ void resid_kernel() {
    __shared__ double sm[256];
    int tid = threadIdx.x, row = blockIdx.x * 256 + tid;
    double local = 0.0;
    if (row < N_PTS) {
        float beta = g_par[1], sg = g_par[2], gm = g_par[3], mu = g_par[4], Cc = g_par[5];
        float ys = g_y[row * 5 + 0], ye = g_y[row * 5 + 1], yi = g_y[row * 5 + 2], yd = g_y[row * 5 + 4];
        float inf = beta * ys * yi / (1.0f - yd);
        float f0 = -inf, f1 = inf - sg * ye, f2 = sg * ye - (gm + mu) * yi, f3 = gm * yi, f4 = mu * yi;
        float d0 = 0, d1 = 0, d2 = 0, d3 = 0, d4 = 0;
        if (row > 0) {
            const float* cv = &g_conv[(row - 1) * 5];
            d0 = Cc * cv[0]; d1 = Cc * cv[1]; d2 = Cc * cv[2]; d3 = Cc * cv[3]; d4 = Cc * cv[4];
        }
        float r0 = d0 - f0, r1 = d1 - f1, r2 = d2 - f2, r3 = d3 - f3, r4 = d4 - f4;
        local = (double)r0 * r0 + (double)r1 * r1 + (double)r2 * r2 + (double)r3 * r3 + (double)r4 * r4;
    }
    sm[tid] = local;
    __syncthreads();
    for (int s2 = 128; s2; s2 >>= 1) {
        if (tid < s2) sm[tid] += sm[tid + s2];
        __syncthreads();
    }
    if (tid == 0) atomicAdd(&g_acc, sm[0]);
}

__global__ void finalize_kernel(float* __restrict__ out) {
    out[0] = (float)(g_acc / (double)(N_PTS * 5));
}

// ---------------- launch -----------------------------------------------------
extern "C" void kernel_launch(void* const* d_in, const int* in_sizes, int n_in,
                              void* d_out, int out_size) {
    const float* t      = (const float*)d_in[0];
    const float* W_in   = (const float*)d_in[1];
    const float* b_in   = (const float*)d_in[2];
    const float* Wh     = (const float*)d_in[3];   // [5,512,512]
    const float* bh     = (const float*)d_in[4];
    const float* W_out  = (const float*)d_in[5];
    const float* b_out  = (const float*)d_in[6];
    const float* rbeta  = (const float*)d_in[7];
    const float* rsigma = (const float*)d_in[8];
    const float* rgamma = (const float*)d_in[9];
    const float* rmu    = (const float*)d_in[10];
    const float* zalpha = (const float*)d_in[11];
    float* out = (float*)d_out;

    static bool inited = false;
    static __half *ahi0, *alo0, *ahi1, *alo1, *wh;
    if (!inited) {
        cudaGetSymbolAddress((void**)&ahi0, g_Ahi0);
        cudaGetSymbolAddress((void**)&alo0, g_Alo0);
        cudaGetSymbolAddress((void**)&ahi1, g_Ahi1);
        cudaGetSymbolAddress((void**)&alo1, g_Alo1);
        cudaGetSymbolAddress((void**)&wh, g_Wh);
        inited = true;
    }

    setup_kernel<<<1, 256>>>(rbeta, rsigma, rgamma, rmu, zalpha);
    wsplit_kernel<<<(DEPTHM1 * HDIM * HDIM + 255) / 256, 256>>>(Wh);
    layer0_kernel<<<(N_PTS * HDIM) / 256, 256>>>(t, W_in, b_in);

    dim3 gg(4, 128);   // (512/128, 8192/64)
    const int WW = HDIM * HDIM;
    gemm_fp16_kernel<<<gg, 256>>>(ahi0, alo0, wh + 0 * WW, bh + 0 * HDIM, ahi1, alo1);
    gemm_fp16_kernel<<<gg, 256>>>(ahi1, alo1, wh + 1 * WW, bh + 1 * HDIM, ahi0, alo0);
    gemm_fp16_kernel<<<gg, 256>>>(ahi0, alo0, wh + 2 * WW, bh + 2 * HDIM, ahi1, alo1);
    gemm_fp16_kernel<<<gg, 256>>>(ahi1, alo1, wh + 3 * WW, bh + 3 * HDIM, ahi0, alo0);
    gemm_fp16_kernel<<<gg, 256>>>(ahi0, alo0, wh + 4 * WW, bh + 4 * HDIM, ahi1, alo1);

    head_kernel<<<N_PTS / 8, 256>>>(ahi1, alo1, W_out, b_out);
    dpsi_kernel<<<(NM1 * 5 + 255) / 256, 256>>>();
    conv_kernel<<<dim3(32, 32), 256>>>();
    resid_kernel<<<N_PTS / 256, 256>>>();
    finalize_kernel<<<1, 1>>>(out);
}

// round 8
// speedup vs baseline: 1.4625x; 1.1192x over previous
#include <cuda_runtime.h>
#include <cuda_fp16.h>
#include <math.h>
#include <stdint.h>

#define N_PTS 8192
#define HDIM  512
#define NM1   8191
#define DEPTHM1 5

// ---------------- scratch (device globals; no allocations allowed) ----------
__device__ __align__(16) __half g_Ahi0[N_PTS * HDIM];
__device__ __align__(16) __half g_Alo0[N_PTS * HDIM];
__device__ __align__(16) __half g_Ahi1[N_PTS * HDIM];
__device__ __align__(16) __half g_Alo1[N_PTS * HDIM];
__device__ __align__(16) __half g_Wh[DEPTHM1 * HDIM * HDIM];  // [l][k][n] fp16
__device__ float  g_y[N_PTS * 5];
__device__ float  g_dpsi[NM1 * 5];
__device__ float  g_ws[NM1];
__device__ float  g_conv[NM1 * 5];
__device__ float  g_par[6];
__device__ double g_acc;

__device__ __forceinline__ float tanh_acc(float x) {
    float ax = fabsf(x);
    float u = __expf(-2.0f * ax);
    float t = __fdividef(1.0f - u, 1.0f + u);
    return copysignf(t, x);
}

// ---------------- setup: scalar params only ----------------------------------
__global__ void setup_kernel(const float* __restrict__ rb, const float* __restrict__ rs,
                             const float* __restrict__ rg, const float* __restrict__ rm,
                             const float* __restrict__ za_p) {
    if (threadIdx.x == 0) {
        float alpha = 0.6f + 0.4f * (1.0f / (1.0f + expf(-za_p[0])));
        g_par[0] = alpha;
        g_par[1] = log1pf(expf(rb[0]));
        g_par[2] = log1pf(expf(rs[0]));
        g_par[3] = log1pf(expf(rg[0]));
        g_par[4] = log1pf(expf(rm[0]));
        g_par[5] = powf(0.1f, -alpha) / expf(lgammaf(2.0f - alpha));
        g_acc    = 0.0;
    }
}

// ---------------- Caputo weights (parallel) + conv zeroing -------------------
__global__ void ws_init_kernel() {
    int idx = blockIdx.x * blockDim.x + threadIdx.x;
    double ex = 1.0 - (double)g_par[0];
    if (idx < NM1) {
        double w = pow((double)(idx + 1), ex);
        if (idx > 0) w -= pow((double)idx, ex);
        g_ws[idx] = (float)w;
    }
    for (int i = idx; i < NM1 * 5; i += gridDim.x * blockDim.x) g_conv[i] = 0.0f;
}

// ---------------- weights -> fp16 --------------------------------------------
__global__ void wsplit_kernel(const float* __restrict__ W) {
    int i = blockIdx.x * 256 + threadIdx.x;
    if (i < DEPTHM1 * HDIM * HDIM) g_Wh[i] = __float2half(W[i]);
}

// ---------------- layer 0 ----------------------------------------------------
__global__ void layer0_kernel(const float* __restrict__ t, const float* __restrict__ W_in,
                              const float* __restrict__ b_in) {
    int idx = blockIdx.x * blockDim.x + threadIdx.x;
    if (idx >= N_PTS * HDIM) return;
    float h = tanh_acc(t[idx >> 9] * W_in[idx & 511] + b_in[idx & 511]);
    __half hi = __float2half(h);
    g_Ahi0[idx] = hi;
    g_Alo0[idx] = __float2half(h - __half2float(hi));
}

// ---------------- tensor-core GEMM (fp16x2) + bias + tanh --------------------
// C = tanh(A@W + bias); A hi/lo fp16, W fp16. Tile 64m x 128n, BK=16, 8 warps.
// 6-stage cp.async ring (8KB/stage), depth-5 prefetch hides L2/DRAM latency.
#define STAGE_BYTES 8192
#define NSTAGE 6

#define LDSM4(r, addr) asm volatile( \
    "ldmatrix.sync.aligned.m8n8.x4.shared.b16 {%0,%1,%2,%3}, [%4];" \
    : "=r"(r[0]), "=r"(r[1]), "=r"(r[2]), "=r"(r[3]) : "r"(addr))

#define LDSM4T(r, addr) asm volatile( \
    "ldmatrix.sync.aligned.m8n8.x4.trans.shared.b16 {%0,%1,%2,%3}, [%4];" \
    : "=r"(r[0]), "=r"(r[1]), "=r"(r[2]), "=r"(r[3]) : "r"(addr))

#define MMAH(d, a, b0, b1) asm volatile( \
    "mma.sync.aligned.m16n8k16.row.col.f32.f16.f16.f32 " \
    "{%0,%1,%2,%3},{%4,%5,%6,%7},{%8,%9},{%0,%1,%2,%3};" \
    : "+f"(d[0]), "+f"(d[1]), "+f"(d[2]), "+f"(d[3]) \
    : "r"(a[0]), "r"(a[1]), "r"(a[2]), "r"(a[3]), "r"(b0), "r"(b1))

__device__ __forceinline__ void cp16(uint32_t dst, const void* src) {
    asm volatile("cp.async.cg.shared.global [%0], [%1], 16;" :: "r"(dst), "l"(src));
}

__global__ __launch_bounds__(256, 3)
void gemm_fp16_kernel(const __half* __restrict__ Ahi, const __half* __restrict__ Alo,
                      const __half* __restrict__ B,
                      const float* __restrict__ bias,
                      __half* __restrict__ Chi, __half* __restrict__ Clo) {
    __shared__ __align__(128) unsigned char smem[NSTAGE * STAGE_BYTES];
    const int tid  = threadIdx.x;
    const int lane = tid & 31;
    const int wid  = tid >> 5;
    const int wm   = wid & 1;     // m offset 32*wm
    const int wn   = wid >> 1;    // n offset 32*wn
    const int rowBase = blockIdx.y * 64;
    const int colBase = blockIdx.x * 128;
    const uint32_t smemBase = (uint32_t)__cvta_generic_to_shared(smem);

    // A: threads 0-127 load A_hi, 128-255 load A_lo; row=(t&127)>>1, kq=(t&1)*8
    const int arow = (tid & 127) >> 1;
    const int akq  = (tid & 1) * 8;
    const __half* aSrc = ((tid < 128) ? Ahi : Alo) + (size_t)(rowBase + arow) * HDIM + akq;
    const uint32_t aDst = (uint32_t)((tid < 128) ? 0 : 2048) + arow * 32 +
                          ((((uint32_t)(akq >> 3)) ^ ((arow >> 2) & 1)) << 4);
    // B: k=t>>4 (0..15), nq=(t&15)*8  (one 16B chunk per thread)
    const int bk  = tid >> 4;
    const int bnq = (tid & 15) * 8;
    const __half* bSrc = B + (size_t)bk * HDIM + colBase + bnq;
    const uint32_t bDst = 4096u + bk * 256 + ((((uint32_t)(bnq >> 3)) ^ (bk & 7)) << 4);

    float acc[2][4][4];
#pragma unroll
    for (int i = 0; i < 2; i++)
#pragma unroll
        for (int j = 0; j < 4; j++)
#pragma unroll
            for (int r = 0; r < 4; r++) acc[i][j][r] = 0.0f;

    // ---- prologue: issue stages 0..4 ----
#pragma unroll
    for (int s = 0; s < NSTAGE - 1; s++) {
        uint32_t st = smemBase + s * STAGE_BYTES;
        cp16(st + aDst, aSrc + (s << 4));
        cp16(st + bDst, bSrc + ((size_t)s << 13));
        asm volatile("cp.async.commit_group;");
    }

    int bufC = 0;            // consume buffer
    int bufP = NSTAGE - 1;   // produce buffer
    for (int s = 0; s < 32; s++) {
        {   // issue stage s+5 (k wraps harmlessly for the last 5 dummy loads)
            int k0 = ((s + NSTAGE - 1) & 31) << 4;
            uint32_t st = smemBase + bufP * STAGE_BYTES;
            cp16(st + aDst, aSrc + k0);
            cp16(st + bDst, bSrc + ((size_t)k0 << 9));
            asm volatile("cp.async.commit_group;");
            if (++bufP == NSTAGE) bufP = 0;
        }
        asm volatile("cp.async.wait_group 5;");
        __syncthreads();

        const uint32_t st = smemBase + bufC * STAGE_BYTES;
        if (++bufC == NSTAGE) bufC = 0;
        uint32_t a_hi[2][4], a_lo[2][4];
#pragma unroll
        for (int i = 0; i < 2; i++) {
            int r = wm * 32 + i * 16 + (lane & 15);
            uint32_t c = ((uint32_t)(lane >> 4)) ^ ((r >> 2) & 1);
            uint32_t addr = st + r * 32 + (c << 4);
            LDSM4(a_hi[i], addr);
            LDSM4(a_lo[i], addr + 2048);
        }
        uint32_t b[2][4];
#pragma unroll
        for (int j = 0; j < 2; j++) {
            int kr = lane & 15;
            uint32_t c = ((uint32_t)(wn * 4 + j * 2 + (lane >> 4))) ^ (kr & 7);
            uint32_t addr = st + 4096u + kr * 256 + (c << 4);
            LDSM4T(b[j], addr);
        }
#pragma unroll
        for (int i = 0; i < 2; i++) {
#pragma unroll
            for (int j = 0; j < 2; j++) {
                MMAH(acc[i][2 * j],     a_hi[i], b[j][0], b[j][1]);
                MMAH(acc[i][2 * j + 1], a_hi[i], b[j][2], b[j][3]);
                MMAH(acc[i][2 * j],     a_lo[i], b[j][0], b[j][1]);
                MMAH(acc[i][2 * j + 1], a_lo[i], b[j][2], b[j][3]);
            }
        }
        __syncthreads();
    }

    // ---- epilogue: bias + tanh + hi/lo split ----
#pragma unroll
    for (int i = 0; i < 2; i++) {
        int r0 = rowBase + wm * 32 + i * 16 + (lane >> 2);
#pragma unroll
        for (int jj = 0; jj < 4; jj++) {
            int c0 = colBase + wn * 32 + jj * 8 + (lane & 3) * 2;
            float bv0 = __ldg(bias + c0), bv1 = __ldg(bias + c0 + 1);
#pragma unroll
            for (int half = 0; half < 2; half++) {
                int r = r0 + half * 8;
                float x0 = acc[i][jj][2 * half + 0] + bv0;
                float x1 = acc[i][jj][2 * half + 1] + bv1;
                float t0 = tanh_acc(x0), t1 = tanh_acc(x1);
                __half h0 = __float2half(t0), h1 = __float2half(t1);
                __half2 hv; hv.x = h0; hv.y = h1;
                __half2 lv;
                lv.x = __float2half(t0 - __half2float(h0));
                lv.y = __float2half(t1 - __half2float(h1));
                *(__half2*)(Chi + (size_t)r * HDIM + c0) = hv;
                *(__half2*)(Clo + (size_t)r * HDIM + c0) = lv;
            }
        }
    }
}

// ---------------- head + softmax ---------------------------------------------
__global__ void head_kernel(const __half* __restrict__ hhi, const __half* __restrict__ hlo,
                            const float* __restrict__ W_out, const float* __restrict__ b_out) {
    int gw = (blockIdx.x * blockDim.x + threadIdx.x) >> 5;
    int lane = threadIdx.x & 31;
    if (gw >= N_PTS) return;
    const __half* hr = hhi + (size_t)gw * HDIM;
    const __half* lr = hlo + (size_t)gw * HDIM;
    float a0 = 0, a1 = 0, a2 = 0, a3 = 0, a4 = 0;
    for (int k = lane; k < HDIM; k += 32) {
        float hv = __half2float(hr[k]) + __half2float(lr[k]);
        const float* w = W_out + k * 5;
        a0 += hv * w[0]; a1 += hv * w[1]; a2 += hv * w[2]; a3 += hv * w[3]; a4 += hv * w[4];
    }
#pragma unroll
    for (int off = 16; off; off >>= 1) {
        a0 += __shfl_down_sync(~0u, a0, off); a1 += __shfl_down_sync(~0u, a1, off);
        a2 += __shfl_down_sync(~0u, a2, off); a3 += __shfl_down_sync(~0u, a3, off);
        a4 += __shfl_down_sync(~0u, a4, off);
    }
    if (lane == 0) {
        a0 += b_out[0]; a1 += b_out[1]; a2 += b_out[2]; a3 += b_out[3]; a4 += b_out[4];
        float mx = fmaxf(fmaxf(fmaxf(a0, a1), fmaxf(a2, a3)), a4);
        float e0 = expf(a0 - mx), e1 = expf(a1 - mx), e2 = expf(a2 - mx);
        float e3 = expf(a3 - mx), e4 = expf(a4 - mx);
        float inv = 1.0f / (e0 + e1 + e2 + e3 + e4);
        g_y[gw * 5 + 0] = e0 * inv; g_y[gw * 5 + 1] = e1 * inv; g_y[gw * 5 + 2] = e2 * inv;
        g_y[gw * 5 + 3] = e3 * inv; g_y[gw * 5 + 4] = e4 * inv;
    }
}

__global__ void dpsi_kernel() {
    int idx = blockIdx.x * blockDim.x + threadIdx.x;
    if (idx < NM1 * 5) g_dpsi[idx] = g_y[idx + 5] - g_y[idx];
}

// ---------------- causal Toeplitz conv ---------------------------------------
__global__ void conv_kernel() {
    int rx = blockIdx.x, jy = blockIdx.y;
    if (jy > rx) return;
    __shared__ float sws[512];
    __shared__ float sd[256 * 5];
    int tid = threadIdx.x, m = rx * 256 + tid, j0 = jy * 256;
    {
        int j = j0 + tid;
#pragma unroll
        for (int c = 0; c < 5; c++) sd[tid * 5 + c] = (j < NM1) ? g_dpsi[j * 5 + c] : 0.0f;
    }
    int wbase = (rx - jy) * 256 - 255;
    for (int k = tid; k < 512; k += 256) {
        int wi = wbase + k;
        sws[k] = (wi >= 0 && wi < NM1) ? g_ws[wi] : 0.0f;
    }
    __syncthreads();
    float a0 = 0, a1 = 0, a2 = 0, a3 = 0, a4 = 0;
#pragma unroll 8
    for (int jj = 0; jj < 256; jj++) {
        float w = sws[tid + 255 - jj];
        const float* d = &sd[jj * 5];
        a0 += w * d[0]; a1 += w * d[1]; a2 += w * d[2]; a3 += w * d[3]; a4 += w * d[4];
    }
    if (m < NM1) {
        atomicAdd(&g_conv[m * 5 + 0], a0); atomicAdd(&g_conv[m * 5 + 1], a1);
        atomicAdd(&g_conv[m * 5 + 2], a2); atomicAdd(&g_conv[m * 5 + 3], a3);
        atomicAdd(&g_conv[m * 5 + 4], a4);
    }
}

// ---------------- residual + loss --------------------------------------------
__global__ void resid_kernel() {
    __shared__ double sm[256];
    int tid = threadIdx.x, row = blockIdx.x * 256 + tid;
    double local = 0.0;
    if (row < N_PTS) {
        float beta = g_par[1], sg = g_par[2], gm = g_par[3], mu = g_par[4], Cc = g_par[5];
        float ys = g_y[row * 5 + 0], ye = g_y[row * 5 + 1], yi = g_y[row * 5 + 2], yd = g_y[row * 5 + 4];
        float inf = beta * ys * yi / (1.0f - yd);
        float f0 = -inf, f1 = inf - sg * ye, f2 = sg * ye - (gm + mu) * yi, f3 = gm * yi, f4 = mu * yi;
        float d0 = 0, d1 = 0, d2 = 0, d3 = 0, d4 = 0;
        if (row > 0) {
            const float* cv = &g_conv[(row - 1) * 5];
            d0 = Cc * cv[0]; d1 = Cc * cv[1]; d2 = Cc * cv[2]; d3 = Cc * cv[3]; d4 = Cc * cv[4];
        }
        float r0 = d0 - f0, r1 = d1 - f1, r2 = d2 - f2, r3 = d3 - f3, r4 = d4 - f4;
        local = (double)r0 * r0 + (double)r1 * r1 + (double)r2 * r2 + (double)r3 * r3 + (double)r4 * r4;
    }
    sm[tid] = local;
    __syncthreads();
    for (int s2 = 128; s2; s2 >>= 1) {
        if (tid < s2) sm[tid] += sm[tid + s2];
        __syncthreads();
    }
    if (tid == 0) atomicAdd(&g_acc, sm[0]);
}

__global__ void finalize_kernel(float* __restrict__ out) {
    out[0] = (float)(g_acc / (double)(N_PTS * 5));
}

// ---------------- launch -----------------------------------------------------
extern "C" void kernel_launch(void* const* d_in, const int* in_sizes, int n_in,
                              void* d_out, int out_size) {
    const float* t      = (const float*)d_in[0];
    const float* W_in   = (const float*)d_in[1];
    const float* b_in   = (const float*)d_in[2];
    const float* Wh     = (const float*)d_in[3];   // [5,512,512]
    const float* bh     = (const float*)d_in[4];
    const float* W_out  = (const float*)d_in[5];
    const float* b_out  = (const float*)d_in[6];
    const float* rbeta  = (const float*)d_in[7];
    const float* rsigma = (const float*)d_in[8];
    const float* rgamma = (const float*)d_in[9];
    const float* rmu    = (const float*)d_in[10];
    const float* zalpha = (const float*)d_in[11];
    float* out = (float*)d_out;

    static bool inited = false;
    static __half *ahi0, *alo0, *ahi1, *alo1, *wh;
    if (!inited) {
        cudaGetSymbolAddress((void**)&ahi0, g_Ahi0);
        cudaGetSymbolAddress((void**)&alo0, g_Alo0);
        cudaGetSymbolAddress((void**)&ahi1, g_Ahi1);
        cudaGetSymbolAddress((void**)&alo1, g_Alo1);
        cudaGetSymbolAddress((void**)&wh, g_Wh);
        inited = true;
    }

    setup_kernel<<<1, 32>>>(rbeta, rsigma, rgamma, rmu, zalpha);
    ws_init_kernel<<<32, 256>>>();
    wsplit_kernel<<<(DEPTHM1 * HDIM * HDIM + 255) / 256, 256>>>(Wh);
    layer0_kernel<<<(N_PTS * HDIM) / 256, 256>>>(t, W_in, b_in);

    dim3 gg(4, 128);   // (512/128, 8192/64)
    const int WW = HDIM * HDIM;
    gemm_fp16_kernel<<<gg, 256>>>(ahi0, alo0, wh + 0 * WW, bh + 0 * HDIM, ahi1, alo1);
    gemm_fp16_kernel<<<gg, 256>>>(ahi1, alo1, wh + 1 * WW, bh + 1 * HDIM, ahi0, alo0);
    gemm_fp16_kernel<<<gg, 256>>>(ahi0, alo0, wh + 2 * WW, bh + 2 * HDIM, ahi1, alo1);
    gemm_fp16_kernel<<<gg, 256>>>(ahi1, alo1, wh + 3 * WW, bh + 3 * HDIM, ahi0, alo0);
    gemm_fp16_kernel<<<gg, 256>>>(ahi0, alo0, wh + 4 * WW, bh + 4 * HDIM, ahi1, alo1);

    head_kernel<<<N_PTS / 8, 256>>>(ahi1, alo1, W_out, b_out);
    dpsi_kernel<<<(NM1 * 5 + 255) / 256, 256>>>();
    conv_kernel<<<dim3(32, 32), 256>>>();
    resid_kernel<<<N_PTS / 256, 256>>>();
    finalize_kernel<<<1, 1>>>(out);
}

// round 9
// speedup vs baseline: 1.4747x; 1.0083x over previous
#include <cuda_runtime.h>
#include <cuda_fp16.h>
#include <math.h>
#include <stdint.h>

#define N_PTS 8192
#define HDIM  512
#define NM1   8191
#define DEPTHM1 5

// ---------------- scratch (device globals; no allocations allowed) ----------
__device__ __align__(16) __half g_Ahi0[N_PTS * HDIM];
__device__ __align__(16) __half g_Alo0[N_PTS * HDIM];
__device__ __align__(16) __half g_Ahi1[N_PTS * HDIM];
__device__ __align__(16) __half g_Alo1[N_PTS * HDIM];
__device__ __align__(16) __half g_Wh[DEPTHM1 * HDIM * HDIM];  // [l][k][n] fp16
__device__ float  g_y[N_PTS * 5];
__device__ float  g_dpsi[NM1 * 5];
__device__ float  g_ws[NM1];
__device__ float  g_conv[NM1 * 5];
__device__ float  g_par[6];
__device__ double g_acc;

__device__ __forceinline__ float tanh_acc(float x) {
    float ax = fabsf(x);
    float u = __expf(-2.0f * ax);
    float t = __fdividef(1.0f - u, 1.0f + u);
    return copysignf(t, x);
}

// ---------------- setup: scalar params ---------------------------------------
__global__ void setup_kernel(const float* __restrict__ rb, const float* __restrict__ rs,
                             const float* __restrict__ rg, const float* __restrict__ rm,
                             const float* __restrict__ za_p) {
    if (threadIdx.x == 0) {
        float alpha = 0.6f + 0.4f * (1.0f / (1.0f + expf(-za_p[0])));
        g_par[0] = alpha;
        g_par[1] = log1pf(expf(rb[0]));
        g_par[2] = log1pf(expf(rs[0]));
        g_par[3] = log1pf(expf(rg[0]));
        g_par[4] = log1pf(expf(rm[0]));
        g_par[5] = powf(0.1f, -alpha) / expf(lgammaf(2.0f - alpha));
        g_acc    = 0.0;
    }
}

// ---------------- Caputo weights (parallel) + conv zeroing -------------------
__global__ void ws_init_kernel() {
    int idx = blockIdx.x * blockDim.x + threadIdx.x;
    double ex = 1.0 - (double)g_par[0];
    if (idx < NM1) {
        double w = pow((double)(idx + 1), ex);
        if (idx > 0) w -= pow((double)idx, ex);
        g_ws[idx] = (float)w;
    }
    for (int i = idx; i < NM1 * 5; i += gridDim.x * blockDim.x) g_conv[i] = 0.0f;
}

// ---------------- weights -> fp16 --------------------------------------------
__global__ void wsplit_kernel(const float* __restrict__ W) {
    int i = blockIdx.x * 256 + threadIdx.x;
    if (i < DEPTHM1 * HDIM * HDIM) g_Wh[i] = __float2half(W[i]);
}

// ---------------- layer 0 (vectorized: 4 elems/thread) -----------------------
__global__ void layer0_kernel(const float* __restrict__ t, const float* __restrict__ W_in,
                              const float* __restrict__ b_in) {
    int v = blockIdx.x * blockDim.x + threadIdx.x;   // 1M threads, 4 elems each
    if (v >= (N_PTS * HDIM) / 4) return;
    int idx = v * 4;
    int row = idx >> 9;
    int j   = idx & 511;
    float tv = __ldg(t + row);
    float4 w = *(const float4*)(W_in + j);
    float4 b = *(const float4*)(b_in + j);
    float h0 = tanh_acc(tv * w.x + b.x);
    float h1 = tanh_acc(tv * w.y + b.y);
    float h2 = tanh_acc(tv * w.z + b.z);
    float h3 = tanh_acc(tv * w.w + b.w);
    __half p0 = __float2half(h0), p1 = __float2half(h1);
    __half p2 = __float2half(h2), p3 = __float2half(h3);
    __half2 hi01; hi01.x = p0; hi01.y = p1;
    __half2 hi23; hi23.x = p2; hi23.y = p3;
    __half2 lo01, lo23;
    lo01.x = __float2half(h0 - __half2float(p0));
    lo01.y = __float2half(h1 - __half2float(p1));
    lo23.x = __float2half(h2 - __half2float(p2));
    lo23.y = __float2half(h3 - __half2float(p3));
    uint2 hv = make_uint2(*(uint32_t*)&hi01, *(uint32_t*)&hi23);
    uint2 lv = make_uint2(*(uint32_t*)&lo01, *(uint32_t*)&lo23);
    *(uint2*)(g_Ahi0 + idx) = hv;
    *(uint2*)(g_Alo0 + idx) = lv;
}

// ---------------- tensor-core GEMM (fp16x2) + bias + tanh --------------------
// CTA 128m x 128n, BK=16, 8 warps (4m x 2n), warp 32m x 64n, 2 CTAs/SM.
// 6-stage cp.async ring, 12KB/stage (A_hi 4K | A_lo 4K | B 4K).
#define STAGE_BYTES 12288
#define NSTAGE 6
#define GEMM_SMEM (NSTAGE * STAGE_BYTES)

#define LDSM4(r, addr) asm volatile( \
    "ldmatrix.sync.aligned.m8n8.x4.shared.b16 {%0,%1,%2,%3}, [%4];" \
    : "=r"(r[0]), "=r"(r[1]), "=r"(r[2]), "=r"(r[3]) : "r"(addr))

#define LDSM4T(r, addr) asm volatile( \
    "ldmatrix.sync.aligned.m8n8.x4.trans.shared.b16 {%0,%1,%2,%3}, [%4];" \
    : "=r"(r[0]), "=r"(r[1]), "=r"(r[2]), "=r"(r[3]) : "r"(addr))

#define MMAH(d, a, b0, b1) asm volatile( \
    "mma.sync.aligned.m16n8k16.row.col.f32.f16.f16.f32 " \
    "{%0,%1,%2,%3},{%4,%5,%6,%7},{%8,%9},{%0,%1,%2,%3};" \
    : "+f"(d[0]), "+f"(d[1]), "+f"(d[2]), "+f"(d[3]) \
    : "r"(a[0]), "r"(a[1]), "r"(a[2]), "r"(a[3]), "r"(b0), "r"(b1))

__device__ __forceinline__ void cp16(uint32_t dst, const void* src) {
    asm volatile("cp.async.cg.shared.global [%0], [%1], 16;" :: "r"(dst), "l"(src));
}

__global__ __launch_bounds__(256, 2)
void gemm_fp16_kernel(const __half* __restrict__ Ahi, const __half* __restrict__ Alo,
                      const __half* __restrict__ B,
                      const float* __restrict__ bias,
                      __half* __restrict__ Chi, __half* __restrict__ Clo) {
    extern __shared__ __align__(128) unsigned char smem[];
    const int tid  = threadIdx.x;
    const int lane = tid & 31;
    const int wid  = tid >> 5;
    const int wm   = wid & 3;     // m offset 32*wm
    const int wn   = wid >> 2;    // n offset 64*wn
    const int rowBase = blockIdx.y * 128;
    const int colBase = blockIdx.x * 128;
    const uint32_t smemBase = (uint32_t)__cvta_generic_to_shared(smem);

    // A: thread t -> row=t>>1 (0..127), 16B chunk kq=(t&1)*8; hi and lo each.
    const int arow = tid >> 1;
    const int akq  = (tid & 1) * 8;
    const __half* aSrcH = Ahi + (size_t)(rowBase + arow) * HDIM + akq;
    const __half* aSrcL = Alo + (size_t)(rowBase + arow) * HDIM + akq;
    const uint32_t aDst = (uint32_t)(arow * 32) +
                          ((((uint32_t)(akq >> 3)) ^ ((arow >> 2) & 1)) << 4);
    // B: k=t>>4 (0..15), nq=(t&15)*8
    const int bk  = tid >> 4;
    const int bnq = (tid & 15) * 8;
    const __half* bSrc = B + (size_t)bk * HDIM + colBase + bnq;
    const uint32_t bDst = 8192u + bk * 256 + ((((uint32_t)(bnq >> 3)) ^ (bk & 7)) << 4);

    float acc[2][8][4];
#pragma unroll
    for (int i = 0; i < 2; i++)
#pragma unroll
        for (int j = 0; j < 8; j++)
#pragma unroll
            for (int r = 0; r < 4; r++) acc[i][j][r] = 0.0f;

    // ---- prologue: stages 0..4 ----
#pragma unroll
    for (int s = 0; s < NSTAGE - 1; s++) {
        uint32_t st = smemBase + s * STAGE_BYTES;
        cp16(st + aDst, aSrcH + (s << 4));
        cp16(st + aDst + 4096, aSrcL + (s << 4));
        cp16(st + bDst, bSrc + ((size_t)s << 13));
        asm volatile("cp.async.commit_group;");
    }

    int bufC = 0;
    int bufP = NSTAGE - 1;
    for (int s = 0; s < 32; s++) {
        {   // issue stage s+5 (wraps harmlessly at the tail)
            int k0 = ((s + NSTAGE - 1) & 31) << 4;
            uint32_t st = smemBase + bufP * STAGE_BYTES;
            cp16(st + aDst, aSrcH + k0);
            cp16(st + aDst + 4096, aSrcL + k0);
            cp16(st + bDst, bSrc + ((size_t)k0 << 9));
            asm volatile("cp.async.commit_group;");
            if (++bufP == NSTAGE) bufP = 0;
        }
        asm volatile("cp.async.wait_group 5;");
        __syncthreads();

        const uint32_t st = smemBase + bufC * STAGE_BYTES;
        if (++bufC == NSTAGE) bufC = 0;

        uint32_t a_hi[2][4], a_lo[2][4];
#pragma unroll
        for (int i = 0; i < 2; i++) {
            int r = wm * 32 + i * 16 + (lane & 15);
            uint32_t c = ((uint32_t)(lane >> 4)) ^ ((r >> 2) & 1);
            uint32_t addr = st + r * 32 + (c << 4);
            LDSM4(a_hi[i], addr);
            LDSM4(a_lo[i], addr + 4096);
        }
        uint32_t b[4][4];
#pragma unroll
        for (int j = 0; j < 4; j++) {
            int kr = lane & 15;
            uint32_t c = ((uint32_t)(wn * 8 + j * 2 + (lane >> 4))) ^ (kr & 7);
            uint32_t addr = st + 8192u + kr * 256 + (c << 4);
            LDSM4T(b[j], addr);
        }
#pragma unroll
        for (int i = 0; i < 2; i++) {
#pragma unroll
            for (int j = 0; j < 4; j++) {
                MMAH(acc[i][2 * j],     a_hi[i], b[j][0], b[j][1]);
                MMAH(acc[i][2 * j + 1], a_hi[i], b[j][2], b[j][3]);
                MMAH(acc[i][2 * j],     a_lo[i], b[j][0], b[j][1]);
                MMAH(acc[i][2 * j + 1], a_lo[i], b[j][2], b[j][3]);
            }
        }
        __syncthreads();
    }

    // ---- epilogue: bias + tanh + hi/lo split ----
#pragma unroll
    for (int i = 0; i < 2; i++) {
        int r0 = rowBase + wm * 32 + i * 16 + (lane >> 2);
#pragma unroll
        for (int jn = 0; jn < 8; jn++) {
            int c0 = colBase + wn * 64 + jn * 8 + (lane & 3) * 2;
            float bv0 = __ldg(bias + c0), bv1 = __ldg(bias + c0 + 1);
#pragma unroll
            for (int half = 0; half < 2; half++) {
                int r = r0 + half * 8;
                float x0 = acc[i][jn][2 * half + 0] + bv0;
                float x1 = acc[i][jn][2 * half + 1] + bv1;
                float t0 = tanh_acc(x0), t1 = tanh_acc(x1);
                __half h0 = __float2half(t0), h1 = __float2half(t1);
                __half2 hv; hv.x = h0; hv.y = h1;
                __half2 lv;
                lv.x = __float2half(t0 - __half2float(h0));
                lv.y = __float2half(t1 - __half2float(h1));
                *(__half2*)(Chi + (size_t)r * HDIM + c0) = hv;
                *(__half2*)(Clo + (size_t)r * HDIM + c0) = lv;
            }
        }
    }
}

// ---------------- head + softmax ---------------------------------------------
__global__ void head_kernel(const __half* __restrict__ hhi, const __half* __restrict__ hlo,
                            const float* __restrict__ W_out, const float* __restrict__ b_out) {
    int gw = (blockIdx.x * blockDim.x + threadIdx.x) >> 5;
    int lane = threadIdx.x & 31;
    if (gw >= N_PTS) return;
    const __half* hr = hhi + (size_t)gw * HDIM;
    const __half* lr = hlo + (size_t)gw * HDIM;
    float a0 = 0, a1 = 0, a2 = 0, a3 = 0, a4 = 0;
    for (int k = lane; k < HDIM; k += 32) {
        float hv = __half2float(hr[k]) + __half2float(lr[k]);
        const float* w = W_out + k * 5;
        a0 += hv * w[0]; a1 += hv * w[1]; a2 += hv * w[2]; a3 += hv * w[3]; a4 += hv * w[4];
    }
#pragma unroll
    for (int off = 16; off; off >>= 1) {
        a0 += __shfl_down_sync(~0u, a0, off); a1 += __shfl_down_sync(~0u, a1, off);
        a2 += __shfl_down_sync(~0u, a2, off); a3 += __shfl_down_sync(~0u, a3, off);
        a4 += __shfl_down_sync(~0u, a4, off);
    }
    if (lane == 0) {
        a0 += b_out[0]; a1 += b_out[1]; a2 += b_out[2]; a3 += b_out[3]; a4 += b_out[4];
        float mx = fmaxf(fmaxf(fmaxf(a0, a1), fmaxf(a2, a3)), a4);
        float e0 = expf(a0 - mx), e1 = expf(a1 - mx), e2 = expf(a2 - mx);
        float e3 = expf(a3 - mx), e4 = expf(a4 - mx);
        float inv = 1.0f / (e0 + e1 + e2 + e3 + e4);
        g_y[gw * 5 + 0] = e0 * inv; g_y[gw * 5 + 1] = e1 * inv; g_y[gw * 5 + 2] = e2 * inv;
        g_y[gw * 5 + 3] = e3 * inv; g_y[gw * 5 + 4] = e4 * inv;
    }
}

__global__ void dpsi_kernel() {
    int idx = blockIdx.x * blockDim.x + threadIdx.x;
    if (idx < NM1 * 5) g_dpsi[idx] = g_y[idx + 5] - g_y[idx];
}

// ---------------- causal Toeplitz conv ---------------------------------------
__global__ void conv_kernel() {
    int rx = blockIdx.x, jy = blockIdx.y;
    if (jy > rx) return;
    __shared__ float sws[512];
    __shared__ float sd[256 * 5];
    int tid = threadIdx.x, m = rx * 256 + tid, j0 = jy * 256;
    {
        int j = j0 + tid;
#pragma unroll
        for (int c = 0; c < 5; c++) sd[tid * 5 + c] = (j < NM1) ? g_dpsi[j * 5 + c] : 0.0f;
    }
    int wbase = (rx - jy) * 256 - 255;
    for (int k = tid; k < 512; k += 256) {
        int wi = wbase + k;
        sws[k] = (wi >= 0 && wi < NM1) ? g_ws[wi] : 0.0f;
    }
    __syncthreads();
    float a0 = 0, a1 = 0, a2 = 0, a3 = 0, a4 = 0;
#pragma unroll 8
    for (int jj = 0; jj < 256; jj++) {
        float w = sws[tid + 255 - jj];
        const float* d = &sd[jj * 5];
        a0 += w * d[0]; a1 += w * d[1]; a2 += w * d[2]; a3 += w * d[3]; a4 += w * d[4];
    }
    if (m < NM1) {
        atomicAdd(&g_conv[m * 5 + 0], a0); atomicAdd(&g_conv[m * 5 + 1], a1);
        atomicAdd(&g_conv[m * 5 + 2], a2); atomicAdd(&g_conv[m * 5 + 3], a3);
        atomicAdd(&g_conv[m * 5 + 4], a4);
    }
}

// ---------------- residual + loss --------------------------------------------
__global__ void resid_kernel() {
    __shared__ double sm[256];
    int tid = threadIdx.x, row = blockIdx.x * 256 + tid;
    double local = 0.0;
    if (row < N_PTS) {
        float beta = g_par[1], sg = g_par[2], gm = g_par[3], mu = g_par[4], Cc = g_par[5];
        float ys = g_y[row * 5 + 0], ye = g_y[row * 5 + 1], yi = g_y[row * 5 + 2], yd = g_y[row * 5 + 4];
        float inf = beta * ys * yi / (1.0f - yd);
        float f0 = -inf, f1 = inf - sg * ye, f2 = sg * ye - (gm + mu) * yi, f3 = gm * yi, f4 = mu * yi;
        float d0 = 0, d1 = 0, d2 = 0, d3 = 0, d4 = 0;
        if (row > 0) {
            const float* cv = &g_conv[(row - 1) * 5];
            d0 = Cc * cv[0]; d1 = Cc * cv[1]; d2 = Cc * cv[2]; d3 = Cc * cv[3]; d4 = Cc * cv[4];
        }
        float r0 = d0 - f0, r1 = d1 - f1, r2 = d2 - f2, r3 = d3 - f3, r4 = d4 - f4;
        local = (double)r0 * r0 + (double)r1 * r1 + (double)r2 * r2 + (double)r3 * r3 + (double)r4 * r4;
    }
    sm[tid] = local;
    __syncthreads();
    for (int s2 = 128; s2; s2 >>= 1) {
        if (tid < s2) sm[tid] += sm[tid + s2];
        __syncthreads();
    }
    if (tid == 0) atomicAdd(&g_acc, sm[0]);
}

__global__ void finalize_kernel(float* __restrict__ out) {
    out[0] = (float)(g_acc / (double)(N_PTS * 5));
}

// ---------------- launch -----------------------------------------------------
extern "C" void kernel_launch(void* const* d_in, const int* in_sizes, int n_in,
                              void* d_out, int out_size) {
    const float* t      = (const float*)d_in[0];
    const float* W_in   = (const float*)d_in[1];
    const float* b_in   = (const float*)d_in[2];
    const float* Wh     = (const float*)d_in[3];   // [5,512,512]
    const float* bh     = (const float*)d_in[4];
    const float* W_out  = (const float*)d_in[5];
    const float* b_out  = (const float*)d_in[6];
    const float* rbeta  = (const float*)d_in[7];
    const float* rsigma = (const float*)d_in[8];
    const float* rgamma = (const float*)d_in[9];
    const float* rmu    = (const float*)d_in[10];
    const float* zalpha = (const float*)d_in[11];
    float* out = (float*)d_out;

    static bool inited = false;
    static __half *ahi0, *alo0, *ahi1, *alo1, *wh;
    if (!inited) {
        cudaGetSymbolAddress((void**)&ahi0, g_Ahi0);
        cudaGetSymbolAddress((void**)&alo0, g_Alo0);
        cudaGetSymbolAddress((void**)&ahi1, g_Ahi1);
        cudaGetSymbolAddress((void**)&alo1, g_Alo1);
        cudaGetSymbolAddress((void**)&wh, g_Wh);
        cudaFuncSetAttribute(gemm_fp16_kernel,
                             cudaFuncAttributeMaxDynamicSharedMemorySize, GEMM_SMEM);
        inited = true;
    }

    setup_kernel<<<1, 32>>>(rbeta, rsigma, rgamma, rmu, zalpha);
    ws_init_kernel<<<32, 256>>>();
    wsplit_kernel<<<(DEPTHM1 * HDIM * HDIM + 255) / 256, 256>>>(Wh);
    layer0_kernel<<<(N_PTS * HDIM / 4 + 255) / 256, 256>>>(t, W_in, b_in);

    dim3 gg(4, 64);   // (512/128, 8192/128)
    const int WW = HDIM * HDIM;
    gemm_fp16_kernel<<<gg, 256, GEMM_SMEM>>>(ahi0, alo0, wh + 0 * WW, bh + 0 * HDIM, ahi1, alo1);
    gemm_fp16_kernel<<<gg, 256, GEMM_SMEM>>>(ahi1, alo1, wh + 1 * WW, bh + 1 * HDIM, ahi0, alo0);
    gemm_fp16_kernel<<<gg, 256, GEMM_SMEM>>>(ahi0, alo0, wh + 2 * WW, bh + 2 * HDIM, ahi1, alo1);
    gemm_fp16_kernel<<<gg, 256, GEMM_SMEM>>>(ahi1, alo1, wh + 3 * WW, bh + 3 * HDIM, ahi0, alo0);
    gemm_fp16_kernel<<<gg, 256, GEMM_SMEM>>>(ahi0, alo0, wh + 4 * WW, bh + 4 * HDIM, ahi1, alo1);

    head_kernel<<<N_PTS / 8, 256>>>(ahi1, alo1, W_out, b_out);
    dpsi_kernel<<<(NM1 * 5 + 255) / 256, 256>>>();
    conv_kernel<<<dim3(32, 32), 256>>>();
    resid_kernel<<<N_PTS / 256, 256>>>();
    finalize_kernel<<<1, 1>>>(out);
}

// round 10
// speedup vs baseline: 2.4143x; 1.6371x over previous
#include <cuda_runtime.h>
#include <cuda_fp16.h>
#include <math.h>
#include <stdint.h>

#define N_PTS 8192
#define HDIM  512
#define NM1   8191
#define DEPTHM1 5

// ---------------- scratch (device globals; no allocations allowed) ----------
__device__ __align__(16) __half g_A0[N_PTS * HDIM];
__device__ __align__(16) __half g_A1[N_PTS * HDIM];
__device__ __align__(16) __half g_Wh[DEPTHM1 * HDIM * HDIM];  // [l][k][n] fp16
__device__ float  g_y[N_PTS * 5];
__device__ float  g_dpsi[NM1 * 5];
__device__ float  g_ws[NM1];
__device__ float  g_conv[NM1 * 5];
__device__ float  g_par[6];
__device__ double g_acc;

__device__ __forceinline__ float tanh_acc(float x) {
    float ax = fabsf(x);
    float u = __expf(-2.0f * ax);
    float t = __fdividef(1.0f - u, 1.0f + u);
    return copysignf(t, x);
}

// ---------------- setup: scalar params ---------------------------------------
__global__ void setup_kernel(const float* __restrict__ rb, const float* __restrict__ rs,
                             const float* __restrict__ rg, const float* __restrict__ rm,
                             const float* __restrict__ za_p) {
    if (threadIdx.x == 0) {
        float alpha = 0.6f + 0.4f * (1.0f / (1.0f + expf(-za_p[0])));
        g_par[0] = alpha;
        g_par[1] = log1pf(expf(rb[0]));
        g_par[2] = log1pf(expf(rs[0]));
        g_par[3] = log1pf(expf(rg[0]));
        g_par[4] = log1pf(expf(rm[0]));
        g_par[5] = powf(0.1f, -alpha) / expf(lgammaf(2.0f - alpha));
        g_acc    = 0.0;
    }
}

// ---------------- Caputo weights (parallel) + conv zeroing -------------------
__global__ void ws_init_kernel() {
    int idx = blockIdx.x * blockDim.x + threadIdx.x;
    double ex = 1.0 - (double)g_par[0];
    if (idx < NM1) {
        double w = pow((double)(idx + 1), ex);
        if (idx > 0) w -= pow((double)idx, ex);
        g_ws[idx] = (float)w;
    }
    for (int i = idx; i < NM1 * 5; i += gridDim.x * blockDim.x) g_conv[i] = 0.0f;
}

// ---------------- weights -> fp16 --------------------------------------------
__global__ void wsplit_kernel(const float* __restrict__ W) {
    int i = blockIdx.x * 256 + threadIdx.x;
    if (i < DEPTHM1 * HDIM * HDIM) g_Wh[i] = __float2half(W[i]);
}

// ---------------- layer 0 (vectorized: 4 elems/thread, fp16 out) -------------
__global__ void layer0_kernel(const float* __restrict__ t, const float* __restrict__ W_in,
                              const float* __restrict__ b_in) {
    int v = blockIdx.x * blockDim.x + threadIdx.x;
    if (v >= (N_PTS * HDIM) / 4) return;
    int idx = v * 4;
    int row = idx >> 9;
    int j   = idx & 511;
    float tv = __ldg(t + row);
    float4 w = *(const float4*)(W_in + j);
    float4 b = *(const float4*)(b_in + j);
    __half2 h01, h23;
    h01.x = __float2half(tanh_acc(tv * w.x + b.x));
    h01.y = __float2half(tanh_acc(tv * w.y + b.y));
    h23.x = __float2half(tanh_acc(tv * w.z + b.z));
    h23.y = __float2half(tanh_acc(tv * w.w + b.w));
    uint2 hv = make_uint2(*(uint32_t*)&h01, *(uint32_t*)&h23);
    *(uint2*)(g_A0 + idx) = hv;
}

// ---------------- tensor-core GEMM (fp16 single-pass) + bias + tanh ----------
// CTA 128m x 128n, BK=16, 8 warps (4m x 2n), warp 32m x 64n, 2 CTAs/SM.
// 8-stage cp.async ring, 8KB/stage (A 4K | B 4K), ONE barrier per iteration.
#define STAGE_BYTES 8192
#define NSTAGE 8
#define GEMM_SMEM (NSTAGE * STAGE_BYTES)

#define LDSM4(r, addr) asm volatile( \
    "ldmatrix.sync.aligned.m8n8.x4.shared.b16 {%0,%1,%2,%3}, [%4];" \
    : "=r"(r[0]), "=r"(r[1]), "=r"(r[2]), "=r"(r[3]) : "r"(addr))

#define LDSM4T(r, addr) asm volatile( \
    "ldmatrix.sync.aligned.m8n8.x4.trans.shared.b16 {%0,%1,%2,%3}, [%4];" \
    : "=r"(r[0]), "=r"(r[1]), "=r"(r[2]), "=r"(r[3]) : "r"(addr))

#define MMAH(d, a, b0, b1) asm volatile( \
    "mma.sync.aligned.m16n8k16.row.col.f32.f16.f16.f32 " \
    "{%0,%1,%2,%3},{%4,%5,%6,%7},{%8,%9},{%0,%1,%2,%3};" \
    : "+f"(d[0]), "+f"(d[1]), "+f"(d[2]), "+f"(d[3]) \
    : "r"(a[0]), "r"(a[1]), "r"(a[2]), "r"(a[3]), "r"(b0), "r"(b1))

__device__ __forceinline__ void cp16(uint32_t dst, const void* src) {
    asm volatile("cp.async.cg.shared.global [%0], [%1], 16;" :: "r"(dst), "l"(src));
}

__global__ __launch_bounds__(256, 2)
void gemm_fp16_kernel(const __half* __restrict__ A,
                      const __half* __restrict__ B,
                      const float* __restrict__ bias,
                      __half* __restrict__ C) {
    extern __shared__ __align__(128) unsigned char smem[];
    const int tid  = threadIdx.x;
    const int lane = tid & 31;
    const int wid  = tid >> 5;
    const int wm   = wid & 3;     // m offset 32*wm
    const int wn   = wid >> 2;    // n offset 64*wn
    const int rowBase = blockIdx.y * 128;
    const int colBase = blockIdx.x * 128;
    const uint32_t smemBase = (uint32_t)__cvta_generic_to_shared(smem);

    // A: thread t -> row=t>>1 (0..127), 16B chunk kq=(t&1)*8
    const int arow = tid >> 1;
    const int akq  = (tid & 1) * 8;
    const __half* aSrc = A + (size_t)(rowBase + arow) * HDIM + akq;
    const uint32_t aDst = (uint32_t)(arow * 32) +
                          ((((uint32_t)(akq >> 3)) ^ ((arow >> 2) & 1)) << 4);
    // B: k=t>>4 (0..15), nq=(t&15)*8
    const int bk  = tid >> 4;
    const int bnq = (tid & 15) * 8;
    const __half* bSrc = B + (size_t)bk * HDIM + colBase + bnq;
    const uint32_t bDst = 4096u + bk * 256 + ((((uint32_t)(bnq >> 3)) ^ (bk & 7)) << 4);

    float acc[2][8][4];
#pragma unroll
    for (int i = 0; i < 2; i++)
#pragma unroll
        for (int j = 0; j < 8; j++)
#pragma unroll
            for (int r = 0; r < 4; r++) acc[i][j][r] = 0.0f;

    // ---- prologue: stages 0..6 ----
#pragma unroll
    for (int s = 0; s < NSTAGE - 1; s++) {
        uint32_t st = smemBase + s * STAGE_BYTES;
        cp16(st + aDst, aSrc + (s << 4));
        cp16(st + bDst, bSrc + ((size_t)s << 13));
        asm volatile("cp.async.commit_group;");
    }

    int bufC = 0;
    int bufP = NSTAGE - 1;
    for (int s = 0; s < 32; s++) {
        asm volatile("cp.async.wait_group 6;");
        __syncthreads();   // stage s visible to all; all warps done reading stage s-1

        {   // issue stage s+7 into buffer (s-1)%8 (safe: barrier above) — wraps at tail
            int k0 = ((s + NSTAGE - 1) & 31) << 4;
            uint32_t st = smemBase + bufP * STAGE_BYTES;
            cp16(st + aDst, aSrc + k0);
            cp16(st + bDst, bSrc + ((size_t)k0 << 9));
            asm volatile("cp.async.commit_group;");
            if (++bufP == NSTAGE) bufP = 0;
        }

        const uint32_t st = smemBase + bufC * STAGE_BYTES;
        if (++bufC == NSTAGE) bufC = 0;

        uint32_t a[2][4];
#pragma unroll
        for (int i = 0; i < 2; i++) {
            int r = wm * 32 + i * 16 + (lane & 15);
            uint32_t c = ((uint32_t)(lane >> 4)) ^ ((r >> 2) & 1);
            LDSM4(a[i], st + r * 32 + (c << 4));
        }
        uint32_t b[4][4];
#pragma unroll
        for (int j = 0; j < 4; j++) {
            int kr = lane & 15;
            uint32_t c = ((uint32_t)(wn * 8 + j * 2 + (lane >> 4))) ^ (kr & 7);
            LDSM4T(b[j], st + 4096u + kr * 256 + (c << 4));
        }
#pragma unroll
        for (int i = 0; i < 2; i++) {
#pragma unroll
            for (int j = 0; j < 4; j++) {
                MMAH(acc[i][2 * j],     a[i], b[j][0], b[j][1]);
                MMAH(acc[i][2 * j + 1], a[i], b[j][2], b[j][3]);
            }
        }
    }

    // ---- epilogue: bias + tanh -> fp16 ----
#pragma unroll
    for (int i = 0; i < 2; i++) {
        int r0 = rowBase + wm * 32 + i * 16 + (lane >> 2);
#pragma unroll
        for (int jn = 0; jn < 8; jn++) {
            int c0 = colBase + wn * 64 + jn * 8 + (lane & 3) * 2;
            float bv0 = __ldg(bias + c0), bv1 = __ldg(bias + c0 + 1);
#pragma unroll
            for (int half = 0; half < 2; half++) {
                int r = r0 + half * 8;
                float t0 = tanh_acc(acc[i][jn][2 * half + 0] + bv0);
                float t1 = tanh_acc(acc[i][jn][2 * half + 1] + bv1);
                __half2 hv;
                hv.x = __float2half(t0);
                hv.y = __float2half(t1);
                *(__half2*)(C + (size_t)r * HDIM + c0) = hv;
            }
        }
    }
}

// ---------------- head + softmax ---------------------------------------------
__global__ void head_kernel(const __half* __restrict__ h,
                            const float* __restrict__ W_out, const float* __restrict__ b_out) {
    int gw = (blockIdx.x * blockDim.x + threadIdx.x) >> 5;
    int lane = threadIdx.x & 31;
    if (gw >= N_PTS) return;
    const __half* hr = h + (size_t)gw * HDIM;
    float a0 = 0, a1 = 0, a2 = 0, a3 = 0, a4 = 0;
#pragma unroll
    for (int k = lane * 2; k < HDIM; k += 64) {
        __half2 hv2 = *(const __half2*)(hr + k);
        float h0 = __low2float(hv2), h1 = __high2float(hv2);
        const float* w0 = W_out + k * 5;
        const float* w1 = w0 + 5;
        a0 += h0 * w0[0] + h1 * w1[0];
        a1 += h0 * w0[1] + h1 * w1[1];
        a2 += h0 * w0[2] + h1 * w1[2];
        a3 += h0 * w0[3] + h1 * w1[3];
        a4 += h0 * w0[4] + h1 * w1[4];
    }
#pragma unroll
    for (int off = 16; off; off >>= 1) {
        a0 += __shfl_down_sync(~0u, a0, off); a1 += __shfl_down_sync(~0u, a1, off);
        a2 += __shfl_down_sync(~0u, a2, off); a3 += __shfl_down_sync(~0u, a3, off);
        a4 += __shfl_down_sync(~0u, a4, off);
    }
    if (lane == 0) {
        a0 += b_out[0]; a1 += b_out[1]; a2 += b_out[2]; a3 += b_out[3]; a4 += b_out[4];
        float mx = fmaxf(fmaxf(fmaxf(a0, a1), fmaxf(a2, a3)), a4);
        float e0 = expf(a0 - mx), e1 = expf(a1 - mx), e2 = expf(a2 - mx);
        float e3 = expf(a3 - mx), e4 = expf(a4 - mx);
        float inv = 1.0f / (e0 + e1 + e2 + e3 + e4);
        g_y[gw * 5 + 0] = e0 * inv; g_y[gw * 5 + 1] = e1 * inv; g_y[gw * 5 + 2] = e2 * inv;
        g_y[gw * 5 + 3] = e3 * inv; g_y[gw * 5 + 4] = e4 * inv;
    }
}

__global__ void dpsi_kernel() {
    int idx = blockIdx.x * blockDim.x + threadIdx.x;
    if (idx < NM1 * 5) g_dpsi[idx] = g_y[idx + 5] - g_y[idx];
}

// ---------------- causal Toeplitz conv v2 (2 rows/thread, float4 d) ----------
__global__ void conv_kernel() {
    int rx = blockIdx.x, jy = blockIdx.y;
    int M0 = rx * 512, j0 = jy * 256;
    if (j0 > M0 + 511) return;
    __shared__ float sws[768];
    __shared__ float sd[256][8];
    int tid = threadIdx.x;
    int wbase = M0 - j0 - 255;
    for (int k = tid; k < 768; k += 256) {
        int wi = wbase + k;
        sws[k] = (wi >= 0 && wi < NM1) ? g_ws[wi] : 0.0f;
    }
    {
        int j = j0 + tid;
        float4 v = make_float4(0.f, 0.f, 0.f, 0.f);
        float v4 = 0.f;
        if (j < NM1) {
            const float* dp = &g_dpsi[j * 5];
            v = make_float4(dp[0], dp[1], dp[2], dp[3]);
            v4 = dp[4];
        }
        *(float4*)&sd[tid][0] = v;
        sd[tid][4] = v4;
    }
    __syncthreads();

    float p0 = 0, p1 = 0, p2 = 0, p3 = 0, p4 = 0;   // m = M0 + tid
    float q0 = 0, q1 = 0, q2 = 0, q3 = 0, q4 = 0;   // m = M0 + 256 + tid
#pragma unroll 4
    for (int jj = 0; jj < 256; jj++) {
        float4 d = *(float4*)&sd[jj][0];
        float d4 = sd[jj][4];
        float w0 = sws[tid + 255 - jj];
        float w1 = sws[tid + 511 - jj];
        p0 += w0 * d.x; p1 += w0 * d.y; p2 += w0 * d.z; p3 += w0 * d.w; p4 += w0 * d4;
        q0 += w1 * d.x; q1 += w1 * d.y; q2 += w1 * d.z; q3 += w1 * d.w; q4 += w1 * d4;
    }
    int m0 = M0 + tid, m1 = M0 + 256 + tid;
    if (m0 < NM1) {
        atomicAdd(&g_conv[m0 * 5 + 0], p0); atomicAdd(&g_conv[m0 * 5 + 1], p1);
        atomicAdd(&g_conv[m0 * 5 + 2], p2); atomicAdd(&g_conv[m0 * 5 + 3], p3);
        atomicAdd(&g_conv[m0 * 5 + 4], p4);
    }
    if (m1 < NM1) {
        atomicAdd(&g_conv[m1 * 5 + 0], q0); atomicAdd(&g_conv[m1 * 5 + 1], q1);
        atomicAdd(&g_conv[m1 * 5 + 2], q2); atomicAdd(&g_conv[m1 * 5 + 3], q3);
        atomicAdd(&g_conv[m1 * 5 + 4], q4);
    }
}

// ---------------- residual + loss --------------------------------------------
__global__ void resid_kernel() {
    __shared__ double sm[256];
    int tid = threadIdx.x, row = blockIdx.x * 256 + tid;
    double local = 0.0;
    if (row < N_PTS) {
        float beta = g_par[1], sg = g_par[2], gm = g_par[3], mu = g_par[4], Cc = g_par[5];
        float ys = g_y[row * 5 + 0], ye = g_y[row * 5 + 1], yi = g_y[row * 5 + 2], yd = g_y[row * 5 + 4];
        float inf = beta * ys * yi / (1.0f - yd);
        float f0 = -inf, f1 = inf - sg * ye, f2 = sg * ye - (gm + mu) * yi, f3 = gm * yi, f4 = mu * yi;
        float d0 = 0, d1 = 0, d2 = 0, d3 = 0, d4 = 0;
        if (row > 0) {
            const float* cv = &g_conv[(row - 1) * 5];
            d0 = Cc * cv[0]; d1 = Cc * cv[1]; d2 = Cc * cv[2]; d3 = Cc * cv[3]; d4 = Cc * cv[4];
        }
        float r0 = d0 - f0, r1 = d1 - f1, r2 = d2 - f2, r3 = d3 - f3, r4 = d4 - f4;
        local = (double)r0 * r0 + (double)r1 * r1 + (double)r2 * r2 + (double)r3 * r3 + (double)r4 * r4;
    }
    sm[tid] = local;
    __syncthreads();
    for (int s2 = 128; s2; s2 >>= 1) {
        if (tid < s2) sm[tid] += sm[tid + s2];
        __syncthreads();
    }
    if (tid == 0) atomicAdd(&g_acc, sm[0]);
}

__global__ void finalize_kernel(float* __restrict__ out) {
    out[0] = (float)(g_acc / (double)(N_PTS * 5));
}

// ---------------- launch -----------------------------------------------------
extern "C" void kernel_launch(void* const* d_in, const int* in_sizes, int n_in,
                              void* d_out, int out_size) {
    const float* t      = (const float*)d_in[0];
    const float* W_in   = (const float*)d_in[1];
    const float* b_in   = (const float*)d_in[2];
    const float* Wh     = (const float*)d_in[3];   // [5,512,512]
    const float* bh     = (const float*)d_in[4];
    const float* W_out  = (const float*)d_in[5];
    const float* b_out  = (const float*)d_in[6];
    const float* rbeta  = (const float*)d_in[7];
    const float* rsigma = (const float*)d_in[8];
    const float* rgamma = (const float*)d_in[9];
    const float* rmu    = (const float*)d_in[10];
    const float* zalpha = (const float*)d_in[11];
    float* out = (float*)d_out;

    static bool inited = false;
    static __half *a0, *a1, *wh;
    if (!inited) {
        cudaGetSymbolAddress((void**)&a0, g_A0);
        cudaGetSymbolAddress((void**)&a1, g_A1);
        cudaGetSymbolAddress((void**)&wh, g_Wh);
        cudaFuncSetAttribute(gemm_fp16_kernel,
                             cudaFuncAttributeMaxDynamicSharedMemorySize, GEMM_SMEM);
        inited = true;
    }

    setup_kernel<<<1, 32>>>(rbeta, rsigma, rgamma, rmu, zalpha);
    ws_init_kernel<<<32, 256>>>();
    wsplit_kernel<<<(DEPTHM1 * HDIM * HDIM + 255) / 256, 256>>>(Wh);
    layer0_kernel<<<(N_PTS * HDIM / 4 + 255) / 256, 256>>>(t, W_in, b_in);

    dim3 gg(4, 64);   // (512/128, 8192/128)
    const int WW = HDIM * HDIM;
    gemm_fp16_kernel<<<gg, 256, GEMM_SMEM>>>(a0, wh + 0 * WW, bh + 0 * HDIM, a1);
    gemm_fp16_kernel<<<gg, 256, GEMM_SMEM>>>(a1, wh + 1 * WW, bh + 1 * HDIM, a0);
    gemm_fp16_kernel<<<gg, 256, GEMM_SMEM>>>(a0, wh + 2 * WW, bh + 2 * HDIM, a1);
    gemm_fp16_kernel<<<gg, 256, GEMM_SMEM>>>(a1, wh + 3 * WW, bh + 3 * HDIM, a0);
    gemm_fp16_kernel<<<gg, 256, GEMM_SMEM>>>(a0, wh + 4 * WW, bh + 4 * HDIM, a1);

    head_kernel<<<N_PTS / 8, 256>>>(a1, W_out, b_out);
    dpsi_kernel<<<(NM1 * 5 + 255) / 256, 256>>>();
    conv_kernel<<<dim3(16, 32), 256>>>();
    resid_kernel<<<N_PTS / 256, 256>>>();
    finalize_kernel<<<1, 1>>>(out);
}

// round 11
// speedup vs baseline: 2.5591x; 1.0600x over previous
#include <cuda_runtime.h>
#include <cuda_fp16.h>
#include <math.h>
#include <stdint.h>

#define N_PTS 8192
#define HDIM  512
#define NM1   8191
#define DEPTHM1 5

// ---------------- scratch (device globals; no allocations allowed) ----------
__device__ __align__(16) __half g_A0[N_PTS * HDIM];
__device__ __align__(16) __half g_A1[N_PTS * HDIM];
__device__ __align__(16) __half g_Wh[DEPTHM1 * HDIM * HDIM];  // [l][k][n] fp16
__device__ float  g_y[N_PTS * 5];
__device__ float  g_dpsi[NM1 * 5];
__device__ float  g_ws[NM1];
__device__ float  g_conv[NM1 * 5];
__device__ float  g_par[6];
__device__ double g_acc;

// HW tanh (MUFU.TANH, sm_75+): 1 MUFU op, rel err ~2^-11 (same scale as fp16 storage)
__device__ __forceinline__ float tanh_fast(float x) {
    float y;
    asm("tanh.approx.f32 %0, %1;" : "=f"(y) : "f"(x));
    return y;
}

// ---------------- init: params + Caputo weights + conv zeroing (fused) -------
__global__ void init_kernel(const float* __restrict__ rb, const float* __restrict__ rs,
                            const float* __restrict__ rg, const float* __restrict__ rm,
                            const float* __restrict__ za_p) {
    int idx = blockIdx.x * blockDim.x + threadIdx.x;
    float alpha = 0.6f + 0.4f * (1.0f / (1.0f + expf(-za_p[0])));
    if (idx == 0) {
        g_par[0] = alpha;
        g_par[1] = log1pf(expf(rb[0]));
        g_par[2] = log1pf(expf(rs[0]));
        g_par[3] = log1pf(expf(rg[0]));
        g_par[4] = log1pf(expf(rm[0]));
        g_par[5] = powf(0.1f, -alpha) / expf(lgammaf(2.0f - alpha));
        g_acc    = 0.0;
    }
    double ex = 1.0 - (double)alpha;
    if (idx < NM1) {
        double w = pow((double)(idx + 1), ex);
        if (idx > 0) w -= pow((double)idx, ex);
        g_ws[idx] = (float)w;
    }
    for (int i = idx; i < NM1 * 5; i += gridDim.x * blockDim.x) g_conv[i] = 0.0f;
}

// ---------------- weights -> fp16 (8 elems/thread) ---------------------------
__global__ void wsplit_kernel(const float* __restrict__ W) {
    int v = blockIdx.x * 256 + threadIdx.x;
    if (v >= (DEPTHM1 * HDIM * HDIM) / 8) return;
    int i = v * 8;
    float4 w0 = *(const float4*)(W + i);
    float4 w1 = *(const float4*)(W + i + 4);
    __half2 h0, h1, h2, h3;
    h0.x = __float2half(w0.x); h0.y = __float2half(w0.y);
    h1.x = __float2half(w0.z); h1.y = __float2half(w0.w);
    h2.x = __float2half(w1.x); h2.y = __float2half(w1.y);
    h3.x = __float2half(w1.z); h3.y = __float2half(w1.w);
    uint4 packed = make_uint4(*(uint32_t*)&h0, *(uint32_t*)&h1,
                              *(uint32_t*)&h2, *(uint32_t*)&h3);
    *(uint4*)(g_Wh + i) = packed;
}

// ---------------- layer 0 (4 elems/thread, HW tanh, fp16 out) ----------------
__global__ void layer0_kernel(const float* __restrict__ t, const float* __restrict__ W_in,
                              const float* __restrict__ b_in) {
    int v = blockIdx.x * blockDim.x + threadIdx.x;
    if (v >= (N_PTS * HDIM) / 4) return;
    int idx = v * 4;
    int row = idx >> 9;
    int j   = idx & 511;
    float tv = __ldg(t + row);
    float4 w = *(const float4*)(W_in + j);
    float4 b = *(const float4*)(b_in + j);
    __half2 h01, h23;
    h01.x = __float2half(tanh_fast(fmaf(tv, w.x, b.x)));
    h01.y = __float2half(tanh_fast(fmaf(tv, w.y, b.y)));
    h23.x = __float2half(tanh_fast(fmaf(tv, w.z, b.z)));
    h23.y = __float2half(tanh_fast(fmaf(tv, w.w, b.w)));
    uint2 hv = make_uint2(*(uint32_t*)&h01, *(uint32_t*)&h23);
    *(uint2*)(g_A0 + idx) = hv;
}

// ---------------- tensor-core GEMM (fp16 single-pass) + bias + tanh ----------
// CTA 128m x 128n, BK=16, 8 warps (4m x 2n), warp 32m x 64n, 2 CTAs/SM.
// 8-stage cp.async ring, 8KB/stage (A 4K | B 4K), ONE barrier per iteration.
#define STAGE_BYTES 8192
#define NSTAGE 8
#define GEMM_SMEM (NSTAGE * STAGE_BYTES)

#define LDSM4(r, addr) asm volatile( \
    "ldmatrix.sync.aligned.m8n8.x4.shared.b16 {%0,%1,%2,%3}, [%4];" \
    : "=r"(r[0]), "=r"(r[1]), "=r"(r[2]), "=r"(r[3]) : "r"(addr))

#define LDSM4T(r, addr) asm volatile( \
    "ldmatrix.sync.aligned.m8n8.x4.trans.shared.b16 {%0,%1,%2,%3}, [%4];" \
    : "=r"(r[0]), "=r"(r[1]), "=r"(r[2]), "=r"(r[3]) : "r"(addr))

#define MMAH(d, a, b0, b1) asm volatile( \
    "mma.sync.aligned.m16n8k16.row.col.f32.f16.f16.f32 " \
    "{%0,%1,%2,%3},{%4,%5,%6,%7},{%8,%9},{%0,%1,%2,%3};" \
    : "+f"(d[0]), "+f"(d[1]), "+f"(d[2]), "+f"(d[3]) \
    : "r"(a[0]), "r"(a[1]), "r"(a[2]), "r"(a[3]), "r"(b0), "r"(b1))

__device__ __forceinline__ void cp16(uint32_t dst, const void* src) {
    asm volatile("cp.async.cg.shared.global [%0], [%1], 16;" :: "r"(dst), "l"(src));
}

__global__ __launch_bounds__(256, 2)
void gemm_fp16_kernel(const __half* __restrict__ A,
                      const __half* __restrict__ B,
                      const float* __restrict__ bias,
                      __half* __restrict__ C) {
    extern __shared__ __align__(128) unsigned char smem[];
    const int tid  = threadIdx.x;
    const int lane = tid & 31;
    const int wid  = tid >> 5;
    const int wm   = wid & 3;     // m offset 32*wm
    const int wn   = wid >> 2;    // n offset 64*wn
    const int rowBase = blockIdx.y * 128;
    const int colBase = blockIdx.x * 128;
    const uint32_t smemBase = (uint32_t)__cvta_generic_to_shared(smem);

    const int arow = tid >> 1;
    const int akq  = (tid & 1) * 8;
    const __half* aSrc = A + (size_t)(rowBase + arow) * HDIM + akq;
    const uint32_t aDst = (uint32_t)(arow * 32) +
                          ((((uint32_t)(akq >> 3)) ^ ((arow >> 2) & 1)) << 4);
    const int bk  = tid >> 4;
    const int bnq = (tid & 15) * 8;
    const __half* bSrc = B + (size_t)bk * HDIM + colBase + bnq;
    const uint32_t bDst = 4096u + bk * 256 + ((((uint32_t)(bnq >> 3)) ^ (bk & 7)) << 4);

    float acc[2][8][4];
#pragma unroll
    for (int i = 0; i < 2; i++)
#pragma unroll
        for (int j = 0; j < 8; j++)
#pragma unroll
            for (int r = 0; r < 4; r++) acc[i][j][r] = 0.0f;

#pragma unroll
    for (int s = 0; s < NSTAGE - 1; s++) {
        uint32_t st = smemBase + s * STAGE_BYTES;
        cp16(st + aDst, aSrc + (s << 4));
        cp16(st + bDst, bSrc + ((size_t)s << 13));
        asm volatile("cp.async.commit_group;");
    }

    int bufC = 0;
    int bufP = NSTAGE - 1;
    for (int s = 0; s < 32; s++) {
        asm volatile("cp.async.wait_group 6;");
        __syncthreads();

        {   // issue stage s+7 (wraps harmlessly at tail)
            int k0 = ((s + NSTAGE - 1) & 31) << 4;
            uint32_t st = smemBase + bufP * STAGE_BYTES;
            cp16(st + aDst, aSrc + k0);
            cp16(st + bDst, bSrc + ((size_t)k0 << 9));
            asm volatile("cp.async.commit_group;");
            if (++bufP == NSTAGE) bufP = 0;
        }

        const uint32_t st = smemBase + bufC * STAGE_BYTES;
        if (++bufC == NSTAGE) bufC = 0;

        uint32_t a[2][4];
#pragma unroll
        for (int i = 0; i < 2; i++) {
            int r = wm * 32 + i * 16 + (lane & 15);
            uint32_t c = ((uint32_t)(lane >> 4)) ^ ((r >> 2) & 1);
            LDSM4(a[i], st + r * 32 + (c << 4));
        }
        uint32_t b[4][4];
#pragma unroll
        for (int j = 0; j < 4; j++) {
            int kr = lane & 15;
            uint32_t c = ((uint32_t)(wn * 8 + j * 2 + (lane >> 4))) ^ (kr & 7);
            LDSM4T(b[j], st + 4096u + kr * 256 + (c << 4));
        }
#pragma unroll
        for (int i = 0; i < 2; i++) {
#pragma unroll
            for (int j = 0; j < 4; j++) {
                MMAH(acc[i][2 * j],     a[i], b[j][0], b[j][1]);
                MMAH(acc[i][2 * j + 1], a[i], b[j][2], b[j][3]);
            }
        }
    }

    // ---- epilogue: bias + HW tanh -> fp16 ----
#pragma unroll
    for (int i = 0; i < 2; i++) {
        int r0 = rowBase + wm * 32 + i * 16 + (lane >> 2);
#pragma unroll
        for (int jn = 0; jn < 8; jn++) {
            int c0 = colBase + wn * 64 + jn * 8 + (lane & 3) * 2;
            float bv0 = __ldg(bias + c0), bv1 = __ldg(bias + c0 + 1);
#pragma unroll
            for (int half = 0; half < 2; half++) {
                int r = r0 + half * 8;
                float t0 = tanh_fast(acc[i][jn][2 * half + 0] + bv0);
                float t1 = tanh_fast(acc[i][jn][2 * half + 1] + bv1);
                __half2 hv;
                hv.x = __float2half(t0);
                hv.y = __float2half(t1);
                *(__half2*)(C + (size_t)r * HDIM + c0) = hv;
            }
        }
    }
}

// ---------------- head + softmax ---------------------------------------------
__global__ void head_kernel(const __half* __restrict__ h,
                            const float* __restrict__ W_out, const float* __restrict__ b_out) {
    int gw = (blockIdx.x * blockDim.x + threadIdx.x) >> 5;
    int lane = threadIdx.x & 31;
    if (gw >= N_PTS) return;
    const __half* hr = h + (size_t)gw * HDIM;
    float a0 = 0, a1 = 0, a2 = 0, a3 = 0, a4 = 0;
#pragma unroll
    for (int k = lane * 2; k < HDIM; k += 64) {
        __half2 hv2 = *(const __half2*)(hr + k);
        float h0 = __low2float(hv2), h1 = __high2float(hv2);
        const float* w0 = W_out + k * 5;
        const float* w1 = w0 + 5;
        a0 += h0 * w0[0] + h1 * w1[0];
        a1 += h0 * w0[1] + h1 * w1[1];
        a2 += h0 * w0[2] + h1 * w1[2];
        a3 += h0 * w0[3] + h1 * w1[3];
        a4 += h0 * w0[4] + h1 * w1[4];
    }
#pragma unroll
    for (int off = 16; off; off >>= 1) {
        a0 += __shfl_down_sync(~0u, a0, off); a1 += __shfl_down_sync(~0u, a1, off);
        a2 += __shfl_down_sync(~0u, a2, off); a3 += __shfl_down_sync(~0u, a3, off);
        a4 += __shfl_down_sync(~0u, a4, off);
    }
    if (lane == 0) {
        a0 += b_out[0]; a1 += b_out[1]; a2 += b_out[2]; a3 += b_out[3]; a4 += b_out[4];
        float mx = fmaxf(fmaxf(fmaxf(a0, a1), fmaxf(a2, a3)), a4);
        float e0 = expf(a0 - mx), e1 = expf(a1 - mx), e2 = expf(a2 - mx);
        float e3 = expf(a3 - mx), e4 = expf(a4 - mx);
        float inv = 1.0f / (e0 + e1 + e2 + e3 + e4);
        g_y[gw * 5 + 0] = e0 * inv; g_y[gw * 5 + 1] = e1 * inv; g_y[gw * 5 + 2] = e2 * inv;
        g_y[gw * 5 + 3] = e3 * inv; g_y[gw * 5 + 4] = e4 * inv;
    }
}

__global__ void dpsi_kernel() {
    int idx = blockIdx.x * blockDim.x + threadIdx.x;
    if (idx < NM1 * 5) g_dpsi[idx] = g_y[idx + 5] - g_y[idx];
}

// ---------------- causal Toeplitz conv (2 rows/thread, float4 d) -------------
__global__ void conv_kernel() {
    int rx = blockIdx.x, jy = blockIdx.y;
    int M0 = rx * 512, j0 = jy * 256;
    if (j0 > M0 + 511) return;
    __shared__ float sws[768];
    __shared__ float sd[256][8];
    int tid = threadIdx.x;
    int wbase = M0 - j0 - 255;
    for (int k = tid; k < 768; k += 256) {
        int wi = wbase + k;
        sws[k] = (wi >= 0 && wi < NM1) ? g_ws[wi] : 0.0f;
    }
    {
        int j = j0 + tid;
        float4 v = make_float4(0.f, 0.f, 0.f, 0.f);
        float v4 = 0.f;
        if (j < NM1) {
            const float* dp = &g_dpsi[j * 5];
            v = make_float4(dp[0], dp[1], dp[2], dp[3]);
            v4 = dp[4];
        }
        *(float4*)&sd[tid][0] = v;
        sd[tid][4] = v4;
    }
    __syncthreads();

    float p0 = 0, p1 = 0, p2 = 0, p3 = 0, p4 = 0;
    float q0 = 0, q1 = 0, q2 = 0, q3 = 0, q4 = 0;
#pragma unroll 4
    for (int jj = 0; jj < 256; jj++) {
        float4 d = *(float4*)&sd[jj][0];
        float d4 = sd[jj][4];
        float w0 = sws[tid + 255 - jj];
        float w1 = sws[tid + 511 - jj];
        p0 += w0 * d.x; p1 += w0 * d.y; p2 += w0 * d.z; p3 += w0 * d.w; p4 += w0 * d4;
        q0 += w1 * d.x; q1 += w1 * d.y; q2 += w1 * d.z; q3 += w1 * d.w; q4 += w1 * d4;
    }
    int m0 = M0 + tid, m1 = M0 + 256 + tid;
    if (m0 < NM1) {
        atomicAdd(&g_conv[m0 * 5 + 0], p0); atomicAdd(&g_conv[m0 * 5 + 1], p1);
        atomicAdd(&g_conv[m0 * 5 + 2], p2); atomicAdd(&g_conv[m0 * 5 + 3], p3);
        atomicAdd(&g_conv[m0 * 5 + 4], p4);
    }
    if (m1 < NM1) {
        atomicAdd(&g_conv[m1 * 5 + 0], q0); atomicAdd(&g_conv[m1 * 5 + 1], q1);
        atomicAdd(&g_conv[m1 * 5 + 2], q2); atomicAdd(&g_conv[m1 * 5 + 3], q3);
        atomicAdd(&g_conv[m1 * 5 + 4], q4);
    }
}

// ---------------- residual + loss --------------------------------------------
__global__ void resid_kernel() {
    __shared__ double sm[256];
    int tid = threadIdx.x, row = blockIdx.x * 256 + tid;
    double local = 0.0;
    if (row < N_PTS) {
        float beta = g_par[1], sg = g_par[2], gm = g_par[3], mu = g_par[4], Cc = g_par[5];
        float ys = g_y[row * 5 + 0], ye = g_y[row * 5 + 1], yi = g_y[row * 5 + 2], yd = g_y[row * 5 + 4];
        float inf = beta * ys * yi / (1.0f - yd);
        float f0 = -inf, f1 = inf - sg * ye, f2 = sg * ye - (gm + mu) * yi, f3 = gm * yi, f4 = mu * yi;
        float d0 = 0, d1 = 0, d2 = 0, d3 = 0, d4 = 0;
        if (row > 0) {
            const float* cv = &g_conv[(row - 1) * 5];
            d0 = Cc * cv[0]; d1 = Cc * cv[1]; d2 = Cc * cv[2]; d3 = Cc * cv[3]; d4 = Cc * cv[4];
        }
        float r0 = d0 - f0, r1 = d1 - f1, r2 = d2 - f2, r3 = d3 - f3, r4 = d4 - f4;
        local = (double)r0 * r0 + (double)r1 * r1 + (double)r2 * r2 + (double)r3 * r3 + (double)r4 * r4;
    }
    sm[tid] = local;
    __syncthreads();
    for (int s2 = 128; s2; s2 >>= 1) {
        if (tid < s2) sm[tid] += sm[tid + s2];
        __syncthreads();
    }
    if (tid == 0) atomicAdd(&g_acc, sm[0]);
}

__global__ void finalize_kernel(float* __restrict__ out) {
    out[0] = (float)(g_acc / (double)(N_PTS * 5));
}

// ---------------- launch -----------------------------------------------------
extern "C" void kernel_launch(void* const* d_in, const int* in_sizes, int n_in,
                              void* d_out, int out_size) {
    const float* t      = (const float*)d_in[0];
    const float* W_in   = (const float*)d_in[1];
    const float* b_in   = (const float*)d_in[2];
    const float* Wh     = (const float*)d_in[3];   // [5,512,512]
    const float* bh     = (const float*)d_in[4];
    const float* W_out  = (const float*)d_in[5];
    const float* b_out  = (const float*)d_in[6];
    const float* rbeta  = (const float*)d_in[7];
    const float* rsigma = (const float*)d_in[8];
    const float* rgamma = (const float*)d_in[9];
    const float* rmu    = (const float*)d_in[10];
    const float* zalpha = (const float*)d_in[11];
    float* out = (float*)d_out;

    static bool inited = false;
    static __half *a0, *a1, *wh;
    if (!inited) {
        cudaGetSymbolAddress((void**)&a0, g_A0);
        cudaGetSymbolAddress((void**)&a1, g_A1);
        cudaGetSymbolAddress((void**)&wh, g_Wh);
        cudaFuncSetAttribute(gemm_fp16_kernel,
                             cudaFuncAttributeMaxDynamicSharedMemorySize, GEMM_SMEM);
        inited = true;
    }

    init_kernel<<<32, 256>>>(rbeta, rsigma, rgamma, rmu, zalpha);
    wsplit_kernel<<<(DEPTHM1 * HDIM * HDIM / 8 + 255) / 256, 256>>>(Wh);
    layer0_kernel<<<(N_PTS * HDIM / 4 + 255) / 256, 256>>>(t, W_in, b_in);

    dim3 gg(4, 64);   // (512/128, 8192/128) = 256 CTAs, single wave at 2/SM
    const int WW = HDIM * HDIM;
    gemm_fp16_kernel<<<gg, 256, GEMM_SMEM>>>(a0, wh + 0 * WW, bh + 0 * HDIM, a1);
    gemm_fp16_kernel<<<gg, 256, GEMM_SMEM>>>(a1, wh + 1 * WW, bh + 1 * HDIM, a0);
    gemm_fp16_kernel<<<gg, 256, GEMM_SMEM>>>(a0, wh + 2 * WW, bh + 2 * HDIM, a1);
    gemm_fp16_kernel<<<gg, 256, GEMM_SMEM>>>(a1, wh + 3 * WW, bh + 3 * HDIM, a0);
    gemm_fp16_kernel<<<gg, 256, GEMM_SMEM>>>(a0, wh + 4 * WW, bh + 4 * HDIM, a1);

    head_kernel<<<N_PTS / 8, 256>>>(a1, W_out, b_out);
    dpsi_kernel<<<(NM1 * 5 + 255) / 256, 256>>>();
    conv_kernel<<<dim3(16, 32), 256>>>();
    resid_kernel<<<N_PTS / 256, 256>>>();
    finalize_kernel<<<1, 1>>>(out);
}

// round 12
// speedup vs baseline: 2.5608x; 1.0007x over previous
#include <cuda_runtime.h>
#include <cuda_fp16.h>
#include <math.h>
#include <stdint.h>

#define N_PTS 8192
#define HDIM  512
#define NM1   8191
#define DEPTHM1 5

// ---------------- scratch (device globals; no allocations allowed) ----------
__device__ __align__(16) __half g_A0[N_PTS * HDIM];
__device__ __align__(16) __half g_A1[N_PTS * HDIM];
__device__ __align__(16) __half g_Wh[DEPTHM1 * HDIM * HDIM];  // [l][k][n] fp16
__device__ float  g_y[N_PTS * 5];
__device__ float  g_ws[NM1];
__device__ float  g_conv[NM1 * 5];
__device__ float  g_par[6];
__device__ double g_acc;
__device__ unsigned int g_done;   // zero-initialized; self-resetting

// HW tanh (MUFU.TANH): 1 MUFU op, rel err ~2^-11 (below fp16 storage noise)
__device__ __forceinline__ float tanh_fast(float x) {
    float y;
    asm("tanh.approx.f32 %0, %1;" : "=f"(y) : "f"(x));
    return y;
}

// ---------------- prep: params + ws + conv zero + wsplit + layer0 (fused) ----
__global__ void prep_kernel(const float* __restrict__ t, const float* __restrict__ W_in,
                            const float* __restrict__ b_in, const float* __restrict__ Wh,
                            const float* __restrict__ rb, const float* __restrict__ rs,
                            const float* __restrict__ rg, const float* __restrict__ rm,
                            const float* __restrict__ za_p) {
    const int idx  = blockIdx.x * blockDim.x + threadIdx.x;
    const int nthr = gridDim.x * blockDim.x;

    if (idx == 0) {
        float alpha = 0.6f + 0.4f * (1.0f / (1.0f + expf(-za_p[0])));
        g_par[0] = alpha;
        g_par[1] = log1pf(expf(rb[0]));
        g_par[2] = log1pf(expf(rs[0]));
        g_par[3] = log1pf(expf(rg[0]));
        g_par[4] = log1pf(expf(rm[0]));
        g_par[5] = powf(0.1f, -alpha) / expf(lgammaf(2.0f - alpha));
        g_acc    = 0.0;
    }

    // Caputo L1 weights (double precision to avoid cancellation)
    if (idx < NM1) {
        float alpha = 0.6f + 0.4f * (1.0f / (1.0f + expf(-za_p[0])));
        double ex = 1.0 - (double)alpha;
        double w = pow((double)(idx + 1), ex);
        if (idx > 0) w -= pow((double)idx, ex);
        g_ws[idx] = (float)w;
    }

    // zero conv accumulators
    for (int i = idx; i < NM1 * 5; i += nthr) g_conv[i] = 0.0f;

    // weights -> fp16 (8 elems per step)
    for (int v = idx; v < (DEPTHM1 * HDIM * HDIM) / 8; v += nthr) {
        int i = v * 8;
        float4 w0 = *(const float4*)(Wh + i);
        float4 w1 = *(const float4*)(Wh + i + 4);
        __half2 h0, h1, h2, h3;
        h0.x = __float2half(w0.x); h0.y = __float2half(w0.y);
        h1.x = __float2half(w0.z); h1.y = __float2half(w0.w);
        h2.x = __float2half(w1.x); h2.y = __float2half(w1.y);
        h3.x = __float2half(w1.z); h3.y = __float2half(w1.w);
        *(uint4*)(g_Wh + i) = make_uint4(*(uint32_t*)&h0, *(uint32_t*)&h1,
                                         *(uint32_t*)&h2, *(uint32_t*)&h3);
    }

    // layer 0: h = tanh(t*W_in + b_in) -> fp16 (4 elems per step)
    for (int v = idx; v < (N_PTS * HDIM) / 4; v += nthr) {
        int i   = v * 4;
        int row = i >> 9;
        int j   = i & 511;
        float tv = __ldg(t + row);
        float4 w = *(const float4*)(W_in + j);
        float4 b = *(const float4*)(b_in + j);
        __half2 h01, h23;
        h01.x = __float2half(tanh_fast(fmaf(tv, w.x, b.x)));
        h01.y = __float2half(tanh_fast(fmaf(tv, w.y, b.y)));
        h23.x = __float2half(tanh_fast(fmaf(tv, w.z, b.z)));
        h23.y = __float2half(tanh_fast(fmaf(tv, w.w, b.w)));
        *(uint2*)(g_A0 + i) = make_uint2(*(uint32_t*)&h01, *(uint32_t*)&h23);
    }
}

// ---------------- tensor-core GEMM (fp16 single-pass) + bias + tanh ----------
// CTA 128m x 128n, BK=16, 8 warps (4m x 2n), warp 32m x 64n, 2 CTAs/SM.
// 8-stage cp.async ring, 8KB/stage (A 4K | B 4K), ONE barrier per iteration.
#define STAGE_BYTES 8192
#define NSTAGE 8
#define GEMM_SMEM (NSTAGE * STAGE_BYTES)

#define LDSM4(r, addr) asm volatile( \
    "ldmatrix.sync.aligned.m8n8.x4.shared.b16 {%0,%1,%2,%3}, [%4];" \
    : "=r"(r[0]), "=r"(r[1]), "=r"(r[2]), "=r"(r[3]) : "r"(addr))

#define LDSM4T(r, addr) asm volatile( \
    "ldmatrix.sync.aligned.m8n8.x4.trans.shared.b16 {%0,%1,%2,%3}, [%4];" \
    : "=r"(r[0]), "=r"(r[1]), "=r"(r[2]), "=r"(r[3]) : "r"(addr))

#define MMAH(d, a, b0, b1) asm volatile( \
    "mma.sync.aligned.m16n8k16.row.col.f32.f16.f16.f32 " \
    "{%0,%1,%2,%3},{%4,%5,%6,%7},{%8,%9},{%0,%1,%2,%3};" \
    : "+f"(d[0]), "+f"(d[1]), "+f"(d[2]), "+f"(d[3]) \
    : "r"(a[0]), "r"(a[1]), "r"(a[2]), "r"(a[3]), "r"(b0), "r"(b1))

__device__ __forceinline__ void cp16(uint32_t dst, const void* src) {
    asm volatile("cp.async.cg.shared.global [%0], [%1], 16;" :: "r"(dst), "l"(src));
}

__global__ __launch_bounds__(256, 2)
void gemm_fp16_kernel(const __half* __restrict__ A,
                      const __half* __restrict__ B,
                      const float* __restrict__ bias,
                      __half* __restrict__ C) {
    extern __shared__ __align__(128) unsigned char smem[];
    const int tid  = threadIdx.x;
    const int lane = tid & 31;
    const int wid  = tid >> 5;
    const int wm   = wid & 3;
    const int wn   = wid >> 2;
    const int rowBase = blockIdx.y * 128;
    const int colBase = blockIdx.x * 128;
    const uint32_t smemBase = (uint32_t)__cvta_generic_to_shared(smem);

    const int arow = tid >> 1;
    const int akq  = (tid & 1) * 8;
    const __half* aSrc = A + (size_t)(rowBase + arow) * HDIM + akq;
    const uint32_t aDst = (uint32_t)(arow * 32) +
                          ((((uint32_t)(akq >> 3)) ^ ((arow >> 2) & 1)) << 4);
    const int bk  = tid >> 4;
    const int bnq = (tid & 15) * 8;
    const __half* bSrc = B + (size_t)bk * HDIM + colBase + bnq;
    const uint32_t bDst = 4096u + bk * 256 + ((((uint32_t)(bnq >> 3)) ^ (bk & 7)) << 4);

    float acc[2][8][4];
#pragma unroll
    for (int i = 0; i < 2; i++)
#pragma unroll
        for (int j = 0; j < 8; j++)
#pragma unroll
            for (int r = 0; r < 4; r++) acc[i][j][r] = 0.0f;

#pragma unroll
    for (int s = 0; s < NSTAGE - 1; s++) {
        uint32_t st = smemBase + s * STAGE_BYTES;
        cp16(st + aDst, aSrc + (s << 4));
        cp16(st + bDst, bSrc + ((size_t)s << 13));
        asm volatile("cp.async.commit_group;");
    }

    int bufC = 0;
    int bufP = NSTAGE - 1;
    for (int s = 0; s < 32; s++) {
        asm volatile("cp.async.wait_group 6;");
        __syncthreads();

        {
            int k0 = ((s + NSTAGE - 1) & 31) << 4;
            uint32_t st = smemBase + bufP * STAGE_BYTES;
            cp16(st + aDst, aSrc + k0);
            cp16(st + bDst, bSrc + ((size_t)k0 << 9));
            asm volatile("cp.async.commit_group;");
            if (++bufP == NSTAGE) bufP = 0;
        }

        const uint32_t st = smemBase + bufC * STAGE_BYTES;
        if (++bufC == NSTAGE) bufC = 0;

        uint32_t a[2][4];
#pragma unroll
        for (int i = 0; i < 2; i++) {
            int r = wm * 32 + i * 16 + (lane & 15);
            uint32_t c = ((uint32_t)(lane >> 4)) ^ ((r >> 2) & 1);
            LDSM4(a[i], st + r * 32 + (c << 4));
        }
        uint32_t b[4][4];
#pragma unroll
        for (int j = 0; j < 4; j++) {
            int kr = lane & 15;
            uint32_t c = ((uint32_t)(wn * 8 + j * 2 + (lane >> 4))) ^ (kr & 7);
            LDSM4T(b[j], st + 4096u + kr * 256 + (c << 4));
        }
#pragma unroll
        for (int i = 0; i < 2; i++) {
#pragma unroll
            for (int j = 0; j < 4; j++) {
                MMAH(acc[i][2 * j],     a[i], b[j][0], b[j][1]);
                MMAH(acc[i][2 * j + 1], a[i], b[j][2], b[j][3]);
            }
        }
    }

    // ---- epilogue: bias + HW tanh -> fp16 ----
#pragma unroll
    for (int i = 0; i < 2; i++) {
        int r0 = rowBase + wm * 32 + i * 16 + (lane >> 2);
#pragma unroll
        for (int jn = 0; jn < 8; jn++) {
            int c0 = colBase + wn * 64 + jn * 8 + (lane & 3) * 2;
            float bv0 = __ldg(bias + c0), bv1 = __ldg(bias + c0 + 1);
#pragma unroll
            for (int half = 0; half < 2; half++) {
                int r = r0 + half * 8;
                float t0 = tanh_fast(acc[i][jn][2 * half + 0] + bv0);
                float t1 = tanh_fast(acc[i][jn][2 * half + 1] + bv1);
                __half2 hv;
                hv.x = __float2half(t0);
                hv.y = __float2half(t1);
                *(__half2*)(C + (size_t)r * HDIM + c0) = hv;
            }
        }
    }
}

// ---------------- head + softmax (4 halves/iter) ------------------------------
__global__ void head_kernel(const __half* __restrict__ h,
                            const float* __restrict__ W_out, const float* __restrict__ b_out) {
    int gw = (blockIdx.x * blockDim.x + threadIdx.x) >> 5;
    int lane = threadIdx.x & 31;
    if (gw >= N_PTS) return;
    const __half* hr = h + (size_t)gw * HDIM;
    float a0 = 0, a1 = 0, a2 = 0, a3 = 0, a4 = 0;
#pragma unroll
    for (int k = lane * 4; k < HDIM; k += 128) {
        uint2 raw = *(const uint2*)(hr + k);
        __half2 p01 = *(__half2*)&raw.x;
        __half2 p23 = *(__half2*)&raw.y;
        float h0 = __low2float(p01), h1 = __high2float(p01);
        float h2 = __low2float(p23), h3 = __high2float(p23);
        const float* w = W_out + k * 5;
        a0 += h0 * w[0] + h1 * w[5] + h2 * w[10] + h3 * w[15];
        a1 += h0 * w[1] + h1 * w[6] + h2 * w[11] + h3 * w[16];
        a2 += h0 * w[2] + h1 * w[7] + h2 * w[12] + h3 * w[17];
        a3 += h0 * w[3] + h1 * w[8] + h2 * w[13] + h3 * w[18];
        a4 += h0 * w[4] + h1 * w[9] + h2 * w[14] + h3 * w[19];
    }
#pragma unroll
    for (int off = 16; off; off >>= 1) {
        a0 += __shfl_down_sync(~0u, a0, off); a1 += __shfl_down_sync(~0u, a1, off);
        a2 += __shfl_down_sync(~0u, a2, off); a3 += __shfl_down_sync(~0u, a3, off);
        a4 += __shfl_down_sync(~0u, a4, off);
    }
    if (lane == 0) {
        a0 += b_out[0]; a1 += b_out[1]; a2 += b_out[2]; a3 += b_out[3]; a4 += b_out[4];
        float mx = fmaxf(fmaxf(fmaxf(a0, a1), fmaxf(a2, a3)), a4);
        float e0 = expf(a0 - mx), e1 = expf(a1 - mx), e2 = expf(a2 - mx);
        float e3 = expf(a3 - mx), e4 = expf(a4 - mx);
        float inv = 1.0f / (e0 + e1 + e2 + e3 + e4);
        g_y[gw * 5 + 0] = e0 * inv; g_y[gw * 5 + 1] = e1 * inv; g_y[gw * 5 + 2] = e2 * inv;
        g_y[gw * 5 + 3] = e3 * inv; g_y[gw * 5 + 4] = e4 * inv;
    }
}

// ---------------- causal Toeplitz conv (dpsi computed inline from y) ---------
__global__ void conv_kernel() {
    int rx = blockIdx.x, jy = blockIdx.y;
    int M0 = rx * 512, j0 = jy * 256;
    if (j0 > M0 + 511) return;
    __shared__ float sws[768];
    __shared__ float sd[256][8];
    int tid = threadIdx.x;
    int wbase = M0 - j0 - 255;
    for (int k = tid; k < 768; k += 256) {
        int wi = wbase + k;
        sws[k] = (wi >= 0 && wi < NM1) ? g_ws[wi] : 0.0f;
    }
    {
        int j = j0 + tid;
        float d0 = 0, d1 = 0, d2 = 0, d3 = 0, d4 = 0;
        if (j < NM1) {
            const float* yp = &g_y[j * 5];
            d0 = yp[5] - yp[0]; d1 = yp[6] - yp[1]; d2 = yp[7] - yp[2];
            d3 = yp[8] - yp[3]; d4 = yp[9] - yp[4];
        }
        *(float4*)&sd[tid][0] = make_float4(d0, d1, d2, d3);
        sd[tid][4] = d4;
    }
    __syncthreads();

    float p0 = 0, p1 = 0, p2 = 0, p3 = 0, p4 = 0;
    float q0 = 0, q1 = 0, q2 = 0, q3 = 0, q4 = 0;
#pragma unroll 4
    for (int jj = 0; jj < 256; jj++) {
        float4 d = *(float4*)&sd[jj][0];
        float d4 = sd[jj][4];
        float w0 = sws[tid + 255 - jj];
        float w1 = sws[tid + 511 - jj];
        p0 += w0 * d.x; p1 += w0 * d.y; p2 += w0 * d.z; p3 += w0 * d.w; p4 += w0 * d4;
        q0 += w1 * d.x; q1 += w1 * d.y; q2 += w1 * d.z; q3 += w1 * d.w; q4 += w1 * d4;
    }
    int m0 = M0 + tid, m1 = M0 + 256 + tid;
    if (m0 < NM1) {
        atomicAdd(&g_conv[m0 * 5 + 0], p0); atomicAdd(&g_conv[m0 * 5 + 1], p1);
        atomicAdd(&g_conv[m0 * 5 + 2], p2); atomicAdd(&g_conv[m0 * 5 + 3], p3);
        atomicAdd(&g_conv[m0 * 5 + 4], p4);
    }
    if (m1 < NM1) {
        atomicAdd(&g_conv[m1 * 5 + 0], q0); atomicAdd(&g_conv[m1 * 5 + 1], q1);
        atomicAdd(&g_conv[m1 * 5 + 2], q2); atomicAdd(&g_conv[m1 * 5 + 3], q3);
        atomicAdd(&g_conv[m1 * 5 + 4], q4);
    }
}

// ---------------- residual + loss + fused finalize ---------------------------
__global__ void resid_kernel(float* __restrict__ out) {
    __shared__ double sm[256];
    int tid = threadIdx.x, row = blockIdx.x * 256 + tid;
    double local = 0.0;
    if (row < N_PTS) {
        float beta = g_par[1], sg = g_par[2], gm = g_par[3], mu = g_par[4], Cc = g_par[5];
        float ys = g_y[row * 5 + 0], ye = g_y[row * 5 + 1], yi = g_y[row * 5 + 2], yd = g_y[row * 5 + 4];
        float inf = beta * ys * yi / (1.0f - yd);
        float f0 = -inf, f1 = inf - sg * ye, f2 = sg * ye - (gm + mu) * yi, f3 = gm * yi, f4 = mu * yi;
        float d0 = 0, d1 = 0, d2 = 0, d3 = 0, d4 = 0;
        if (row > 0) {
            const float* cv = &g_conv[(row - 1) * 5];
            d0 = Cc * cv[0]; d1 = Cc * cv[1]; d2 = Cc * cv[2]; d3 = Cc * cv[3]; d4 = Cc * cv[4];
        }
        float r0 = d0 - f0, r1 = d1 - f1, r2 = d2 - f2, r3 = d3 - f3, r4 = d4 - f4;
        local = (double)r0 * r0 + (double)r1 * r1 + (double)r2 * r2 + (double)r3 * r3 + (double)r4 * r4;
    }
    sm[tid] = local;
    __syncthreads();
    for (int s2 = 128; s2; s2 >>= 1) {
        if (tid < s2) sm[tid] += sm[tid + s2];
        __syncthreads();
    }
    if (tid == 0) {
        atomicAdd(&g_acc, sm[0]);
        __threadfence();
        unsigned int ticket = atomicAdd(&g_done, 1u);
        if (ticket == gridDim.x - 1) {           // last block: finalize
            out[0] = (float)(g_acc / (double)(N_PTS * 5));
            g_done = 0;                          // reset for next graph replay
        }
    }
}

// ---------------- launch -----------------------------------------------------
extern "C" void kernel_launch(void* const* d_in, const int* in_sizes, int n_in,
                              void* d_out, int out_size) {
    const float* t      = (const float*)d_in[0];
    const float* W_in   = (const float*)d_in[1];
    const float* b_in   = (const float*)d_in[2];
    const float* Wh     = (const float*)d_in[3];   // [5,512,512]
    const float* bh     = (const float*)d_in[4];
    const float* W_out  = (const float*)d_in[5];
    const float* b_out  = (const float*)d_in[6];
    const float* rbeta  = (const float*)d_in[7];
    const float* rsigma = (const float*)d_in[8];
    const float* rgamma = (const float*)d_in[9];
    const float* rmu    = (const float*)d_in[10];
    const float* zalpha = (const float*)d_in[11];
    float* out = (float*)d_out;

    static bool inited = false;
    static __half *a0, *a1, *wh;
    if (!inited) {
        cudaGetSymbolAddress((void**)&a0, g_A0);
        cudaGetSymbolAddress((void**)&a1, g_A1);
        cudaGetSymbolAddress((void**)&wh, g_Wh);
        cudaFuncSetAttribute(gemm_fp16_kernel,
                             cudaFuncAttributeMaxDynamicSharedMemorySize, GEMM_SMEM);
        inited = true;
    }

    prep_kernel<<<1024, 256>>>(t, W_in, b_in, Wh, rbeta, rsigma, rgamma, rmu, zalpha);

    dim3 gg(4, 64);   // (512/128, 8192/128)
    const int WW = HDIM * HDIM;
    gemm_fp16_kernel<<<gg, 256, GEMM_SMEM>>>(a0, wh + 0 * WW, bh + 0 * HDIM, a1);
    gemm_fp16_kernel<<<gg, 256, GEMM_SMEM>>>(a1, wh + 1 * WW, bh + 1 * HDIM, a0);
    gemm_fp16_kernel<<<gg, 256, GEMM_SMEM>>>(a0, wh + 2 * WW, bh + 2 * HDIM, a1);
    gemm_fp16_kernel<<<gg, 256, GEMM_SMEM>>>(a1, wh + 3 * WW, bh + 3 * HDIM, a0);
    gemm_fp16_kernel<<<gg, 256, GEMM_SMEM>>>(a0, wh + 4 * WW, bh + 4 * HDIM, a1);

    head_kernel<<<N_PTS / 8, 256>>>(a1, W_out, b_out);
    conv_kernel<<<dim3(16, 32), 256>>>();
    resid_kernel<<<N_PTS / 256, 256>>>(out);
}